// round 13
// baseline (speedup 1.0000x reference)
#include <cuda_runtime.h>
#include <cuda_fp16.h>
#include <math.h>
#include <stdint.h>

// ---------------- Problem constants ----------------
#define BATCH   2
#define SEQ     2048
#define NTOK    (BATCH*SEQ)          // 4096
#define DMODEL  1024
#define DINNER  2048
#define NHEADS  32
#define HEADDIM 64
#define DSTATE  64
#define DCONV   4
#define CONVDIM 2176                 // DINNER + 2*DSTATE
#define DINPROJ 4256                 // 2*DINNER + 2*DSTATE + NHEADS
#define DMLP    4096
#define EPS     1e-5f

// ---------------- Scratch (device globals; no allocation allowed) ----------------
__device__ float g_zx [NTOK*DINPROJ];
__device__ float g_xbc[NTOK*CONVDIM];
__device__ float g_dt [NTOK*NHEADS];
__device__ float g_y  [NTOK*DINNER];
__device__ float g_x2 [NTOK*DMODEL];
// activation fp16 hi/lo planes (GEMM A operands)
__device__ __half g_h1h[NTOK*DMODEL],  g_h1l[NTOK*DMODEL];
__device__ __half g_ynh[NTOK*DINNER],  g_ynl[NTOK*DINNER];
__device__ __half g_h2h[NTOK*DMODEL],  g_h2l[NTOK*DMODEL];
__device__ __half g_mdh[NTOK*DMLP],    g_mdl[NTOK*DMLP];
// weight fp16 planes (GEMM B operands, hi only)
__device__ __half g_wi[DINPROJ*DMODEL];
__device__ __half g_wo[DMODEL*DINNER];
__device__ __half g_w1[DMLP*DMODEL];
__device__ __half g_w2[DMODEL*DMLP];

// ---------------- f32x2 packed helpers (scan) ----------------
__device__ __forceinline__ unsigned long long pk2(float x, float y) {
    unsigned long long r;
    asm("mov.b64 %0, {%1, %2};" : "=l"(r) : "f"(x), "f"(y));
    return r;
}
__device__ __forceinline__ float2 upk(unsigned long long v) {
    float2 f;
    asm("mov.b64 {%0, %1}, %2;" : "=f"(f.x), "=f"(f.y) : "l"(v));
    return f;
}
__device__ __forceinline__ void fma2(unsigned long long &d, unsigned long long a, unsigned long long b) {
    asm("fma.rn.f32x2 %0, %1, %2, %0;" : "+l"(d) : "l"(a), "l"(b));
}
__device__ __forceinline__ unsigned long long mul2(unsigned long long a, unsigned long long b) {
    unsigned long long r;
    asm("mul.rn.f32x2 %0, %1, %2;" : "=l"(r) : "l"(a), "l"(b));
    return r;
}

// ---------------- mma.sync helpers (portable sm_80+ PTX) ----------------
__device__ __forceinline__ uint32_t smem_u32(const void* p) {
    uint32_t a;
    asm("{ .reg .u64 t; cvta.to.shared.u64 t, %1; cvt.u32.u64 %0, t; }" : "=r"(a) : "l"(p));
    return a;
}
__device__ __forceinline__ void ldsm_x4(uint32_t &r0, uint32_t &r1, uint32_t &r2, uint32_t &r3,
                                        uint32_t addr) {
    asm volatile("ldmatrix.sync.aligned.m8n8.x4.shared.b16 {%0,%1,%2,%3}, [%4];"
                 : "=r"(r0), "=r"(r1), "=r"(r2), "=r"(r3) : "r"(addr));
}
__device__ __forceinline__ void mma_f16(float* c, const uint32_t* a, const uint32_t* b) {
    asm volatile(
        "mma.sync.aligned.m16n8k16.row.col.f32.f16.f16.f32 "
        "{%0,%1,%2,%3}, {%4,%5,%6,%7}, {%8,%9}, {%0,%1,%2,%3};"
        : "+f"(c[0]), "+f"(c[1]), "+f"(c[2]), "+f"(c[3])
        : "r"(a[0]), "r"(a[1]), "r"(a[2]), "r"(a[3]), "r"(b[0]), "r"(b[1]));
}

// ---------------- fp16 hi/lo split ----------------
__device__ __forceinline__ void cvt_split_h(float4 v, uint2 &hi, uint2 &lo) {
    __half2 h0 = __float22half2_rn(make_float2(v.x, v.y));
    __half2 h1 = __float22half2_rn(make_float2(v.z, v.w));
    float2 f0 = __half22float2(h0);
    float2 f1 = __half22float2(h1);
    __half2 l0 = __float22half2_rn(make_float2(v.x - f0.x, v.y - f0.y));
    __half2 l1 = __float22half2_rn(make_float2(v.z - f1.x, v.w - f1.y));
    hi.x = *(uint32_t*)&h0; hi.y = *(uint32_t*)&h1;
    lo.x = *(uint32_t*)&l0; lo.y = *(uint32_t*)&l1;
}

// ---------------- weight convert: fp32 -> fp16 ----------------
__global__ __launch_bounds__(256) void wcvt_kernel(
    const float* __restrict__ src, __half* __restrict__ dst, int n4)
{
    int i = blockIdx.x * 256 + threadIdx.x;
    if (i >= n4) return;
    float4 v = ((const float4*)src)[i];
    __half2 h0 = __float22half2_rn(make_float2(v.x, v.y));
    __half2 h1 = __float22half2_rn(make_float2(v.z, v.w));
    uint2 h;
    h.x = *(uint32_t*)&h0; h.y = *(uint32_t*)&h1;
    ((uint2*)dst)[i] = h;
}

// ---------------- block reduction (256 threads) ----------------
__device__ __forceinline__ float block_sum256(float v) {
    __shared__ float sb[8];
    #pragma unroll
    for (int o = 16; o; o >>= 1) v += __shfl_xor_sync(0xffffffffu, v, o);
    int w = threadIdx.x >> 5;
    if ((threadIdx.x & 31) == 0) sb[w] = v;
    __syncthreads();
    if (threadIdx.x == 0) {
        float t = 0.f;
        #pragma unroll
        for (int i = 0; i < 8; i++) t += sb[i];
        sb[0] = t;
    }
    __syncthreads();
    float r = sb[0];
    __syncthreads();
    return r;
}

// ---------------- LayerNorm: rows of 1024, writes fp16 hi/lo planes ----------------
__global__ __launch_bounds__(256) void ln_split_kernel(
    const float* __restrict__ x, const float* __restrict__ w,
    const float* __restrict__ b, __half* __restrict__ oh, __half* __restrict__ ol)
{
    int row = blockIdx.x, tid = threadIdx.x;
    const float4* xr = (const float4*)(x + (size_t)row * DMODEL);
    float4 v = xr[tid];
    float mu = block_sum256(v.x + v.y + v.z + v.w) * (1.f / DMODEL);
    float4 d = {v.x - mu, v.y - mu, v.z - mu, v.w - mu};
    float var = block_sum256(d.x*d.x + d.y*d.y + d.z*d.z + d.w*d.w) * (1.f / DMODEL);
    float rs = rsqrtf(var + EPS);
    float4 wv = ((const float4*)w)[tid];
    float4 bv = ((const float4*)b)[tid];
    float4 o = {d.x*rs*wv.x + bv.x, d.y*rs*wv.y + bv.y, d.z*rs*wv.z + bv.z, d.w*rs*wv.w + bv.w};
    uint2 h, l;
    cvt_split_h(o, h, l);
    ((uint2*)(oh + (size_t)row * DMODEL))[tid] = h;
    ((uint2*)(ol + (size_t)row * DMODEL))[tid] = l;
}

// ---------------- GEMM via mma.sync: C[M,N] = A[M,K] @ B[N,K]^T (+ epilogue) ----------------
// A as fp16 hi/lo planes, B as single fp16. 2-term: (Ah + Al) * Bh, fp32 accumulate.
// EPI: 0 = none, 1 = bias+gelu(exact), 2 = +res, 3 = +bias+res
// OUTP: 0 = fp32 C, 1 = fp16 hi/lo planes (Chi/Clo)
template<int EPI>
__device__ __forceinline__ float epi_f(float v, int gn, const float* __restrict__ bias,
                                       const float* __restrict__ rrow) {
    if (EPI == 1) { v += bias[gn]; return 0.5f * v * (1.f + erff(v * 0.70710678118654752f)); }
    if (EPI == 2) return v + rrow[gn];
    if (EPI == 3) return v + bias[gn] + rrow[gn];
    return v;
}

#define ROWB   80                    // bytes per SMEM row: 32 fp16 data + 8 pad
#define PLANE  (128*ROWB)            // 10240 B
#define STAGEB (3*PLANE)             // Ah, Al, Bh = 30720 B
#define GEMM_SMEM (2*STAGEB)         // 61440 B

template<int EPI, int OUTP>
__global__ __launch_bounds__(256, 1) void gemm_mma(
    const __half* __restrict__ Ahp, const __half* __restrict__ Alp,
    const __half* __restrict__ Bhp,
    float* __restrict__ C, __half* __restrict__ Chi, __half* __restrict__ Clo,
    int M, int N, int K, const float* __restrict__ bias, const float* __restrict__ res)
{
    extern __shared__ char smem[];
    const int tid = threadIdx.x;
    const int m0 = blockIdx.y * 128, n0 = blockIdx.x * 128;
    const int warp = tid >> 5, lane = tid & 31;
    const int wm = (warp & 1) * 64;      // warp grid: 2 along M
    const int wn = (warp >> 1) * 32;     // 4 along N

    // loader: thread covers 8 fp16 (16B) at k-offset (tid&3)*8 of rows rq and rq+64
    const int rq = tid >> 2;             // 0..63
    const int kc = (tid & 3) * 8;
    const __half* Ah0 = Ahp + (size_t)(m0 + rq) * K + kc;
    const __half* Al0 = Alp + (size_t)(m0 + rq) * K + kc;
    const __half* Bh0 = Bhp + (size_t)(n0 + rq) * K + kc;
    const size_t rstep = (size_t)64 * K;
    const bool bok0 = (n0 + rq) < N;
    const bool bok1 = (n0 + rq + 64) < N;
    const uint32_t wb = (uint32_t)rq * ROWB + (tid & 3) * 16;

    const uint32_t sbase = smem_u32(smem);

    float acc[4][4][4];
    #pragma unroll
    for (int mt = 0; mt < 4; mt++)
        #pragma unroll
        for (int nt = 0; nt < 4; nt++)
            #pragma unroll
            for (int r = 0; r < 4; r++) acc[mt][nt][r] = 0.f;

    const uint4 z4 = {0u, 0u, 0u, 0u};
    uint4 vah0, vah1, val0, val1, vbh0, vbh1;

    // prologue: chunk 0 -> stage 0
    vah0 = *(const uint4*)(Ah0);
    vah1 = *(const uint4*)(Ah0 + rstep);
    val0 = *(const uint4*)(Al0);
    val1 = *(const uint4*)(Al0 + rstep);
    vbh0 = bok0 ? *(const uint4*)(Bh0) : z4;
    vbh1 = bok1 ? *(const uint4*)(Bh0 + rstep) : z4;
    {
        char* st = smem;
        *(uint4*)(st + 0 * PLANE + wb)            = vah0;
        *(uint4*)(st + 0 * PLANE + wb + 64*ROWB)  = vah1;
        *(uint4*)(st + 1 * PLANE + wb)            = val0;
        *(uint4*)(st + 1 * PLANE + wb + 64*ROWB)  = val1;
        *(uint4*)(st + 2 * PLANE + wb)            = vbh0;
        *(uint4*)(st + 2 * PLANE + wb + 64*ROWB)  = vbh1;
    }
    __syncthreads();

    const int nch = K >> 5;   // K/32
    for (int c = 0; c < nch; c++) {
        const int cur = c & 1;
        const uint32_t sb = sbase + cur * STAGEB;

        if (c + 1 < nch) {
            const size_t kf = (size_t)(c + 1) * 32;
            vah0 = *(const uint4*)(Ah0 + kf);
            vah1 = *(const uint4*)(Ah0 + kf + rstep);
            val0 = *(const uint4*)(Al0 + kf);
            val1 = *(const uint4*)(Al0 + kf + rstep);
            vbh0 = bok0 ? *(const uint4*)(Bh0 + kf) : z4;
            vbh1 = bok1 ? *(const uint4*)(Bh0 + kf + rstep) : z4;
        }

        // compute: 2 k16 steps
        #pragma unroll
        for (int ks = 0; ks < 2; ks++) {
            const uint32_t kb = ks * 32;
            uint32_t ah[4][4], al[4][4], bh[4][2];
            #pragma unroll
            for (int mt = 0; mt < 4; mt++) {
                uint32_t ar = sb + (uint32_t)(wm + mt * 16 + (lane & 15)) * ROWB
                            + kb + ((lane >> 4) << 4);
                ldsm_x4(ah[mt][0], ah[mt][1], ah[mt][2], ah[mt][3], ar);
                ldsm_x4(al[mt][0], al[mt][1], al[mt][2], al[mt][3], ar + PLANE);
            }
            const int g = lane >> 3;
            #pragma unroll
            for (int pr = 0; pr < 2; pr++) {
                uint32_t br = sb + 2 * PLANE
                            + (uint32_t)(wn + pr * 16 + ((g >> 1) << 3) + (lane & 7)) * ROWB
                            + kb + ((g & 1) << 4);
                uint32_t r0, r1, r2, r3;
                ldsm_x4(r0, r1, r2, r3, br);
                bh[2*pr][0] = r0; bh[2*pr][1] = r1; bh[2*pr+1][0] = r2; bh[2*pr+1][1] = r3;
            }
            #pragma unroll
            for (int mt = 0; mt < 4; mt++)
                #pragma unroll
                for (int nt = 0; nt < 4; nt++) {
                    mma_f16(acc[mt][nt], ah[mt], bh[nt]);
                    mma_f16(acc[mt][nt], al[mt], bh[nt]);
                }
        }

        if (c + 1 < nch) {
            char* st = smem + (cur ^ 1) * STAGEB;
            *(uint4*)(st + 0 * PLANE + wb)            = vah0;
            *(uint4*)(st + 0 * PLANE + wb + 64*ROWB)  = vah1;
            *(uint4*)(st + 1 * PLANE + wb)            = val0;
            *(uint4*)(st + 1 * PLANE + wb + 64*ROWB)  = val1;
            *(uint4*)(st + 2 * PLANE + wb)            = vbh0;
            *(uint4*)(st + 2 * PLANE + wb + 64*ROWB)  = vbh1;
        }
        __syncthreads();
    }

    // epilogue: frag c0=(r, col) c1=(r, col+1) c2=(r+8, col) c3=(r+8, col+1)
    #pragma unroll
    for (int mt = 0; mt < 4; mt++) {
        const int gr = m0 + wm + mt * 16 + (lane >> 2);
        const float* R0 = (EPI >= 2) ? (res + (size_t)gr * N) : (const float*)0;
        const float* R1 = (EPI >= 2) ? (res + (size_t)(gr + 8) * N) : (const float*)0;
        #pragma unroll
        for (int nt = 0; nt < 4; nt++) {
            const int gc = n0 + wn + nt * 8 + (lane & 3) * 2;
            if (gc < N) {
                float2 v0 = { epi_f<EPI>(acc[mt][nt][0], gc,     bias, R0),
                              epi_f<EPI>(acc[mt][nt][1], gc + 1, bias, R0) };
                float2 v1 = { epi_f<EPI>(acc[mt][nt][2], gc,     bias, R1),
                              epi_f<EPI>(acc[mt][nt][3], gc + 1, bias, R1) };
                if (OUTP == 0) {
                    *(float2*)(C + (size_t)gr * N + gc) = v0;
                    *(float2*)(C + (size_t)(gr + 8) * N + gc) = v1;
                } else {
                    __half2 h0 = __float22half2_rn(v0);
                    float2 f0 = __half22float2(h0);
                    __half2 l0 = __float22half2_rn(make_float2(v0.x - f0.x, v0.y - f0.y));
                    __half2 h1 = __float22half2_rn(v1);
                    float2 f1 = __half22float2(h1);
                    __half2 l1 = __float22half2_rn(make_float2(v1.x - f1.x, v1.y - f1.y));
                    *(__half2*)(Chi + (size_t)gr * N + gc) = h0;
                    *(__half2*)(Clo + (size_t)gr * N + gc) = l0;
                    *(__half2*)(Chi + (size_t)(gr + 8) * N + gc) = h1;
                    *(__half2*)(Clo + (size_t)(gr + 8) * N + gc) = l1;
                }
            }
        }
    }
}

// ---------------- dt = softplus(zx[..., 4224:4256] + dt_bias) ----------------
__global__ __launch_bounds__(256) void dt_kernel(
    const float* __restrict__ zx, const float* __restrict__ dt_bias, float* __restrict__ dt)
{
    int idx = blockIdx.x * 256 + threadIdx.x;  // NTOK*32
    int t = idx >> 5, h = idx & 31;
    float v = zx[(size_t)t * DINPROJ + (DINNER + CONVDIM) + h] + dt_bias[h];
    dt[idx] = (v > 20.f) ? v : log1pf(__expf(v));
}

// ---------------- causal depthwise conv(4) + silu ----------------
__global__ __launch_bounds__(256) void conv_kernel(
    const float* __restrict__ zx, const float* __restrict__ cw,
    const float* __restrict__ cb, float* __restrict__ xbc)
{
    int c = blockIdx.x * 256 + threadIdx.x;
    if (c >= CONVDIM) return;
    int t = blockIdx.y;
    int b = t >> 11, tl = t & 2047;
    float acc = cb[c];
    const float* src = zx + (size_t)b * SEQ * DINPROJ + DINNER + c;
    #pragma unroll
    for (int k = 0; k < DCONV; k++) {
        int ts = tl - 3 + k;
        if (ts >= 0) acc += src[(size_t)ts * DINPROJ] * cw[c * DCONV + k];
    }
    float s = acc / (1.f + __expf(-acc));
    xbc[(size_t)t * CONVDIM + c] = s;
}

// ---------------- SSM sequential scan ----------------
__global__ __launch_bounds__(256) void scan_kernel(
    const float* __restrict__ xbc, const float* __restrict__ dtp,
    const float* __restrict__ A_log, const float* __restrict__ Dp,
    float* __restrict__ y)
{
    const int CH = 16;
    __shared__ float sx[2][CH][64], sB[2][CH][64], sC[2][CH][64];
    __shared__ float sdt[2][CH], sdA[2][CH];
    const int bh = blockIdx.x, b = bh >> 5, h = bh & 31;
    const int tid = threadIdx.x, p = tid >> 2, q = tid & 3;
    const float Ac = -expf(A_log[h]);
    const float Dv = Dp[h];
    const float* base = xbc + (size_t)b * SEQ * CONVDIM;
    const float* dtb  = dtp + (size_t)b * SEQ * NHEADS + h;
    float* yb = y + (size_t)b * SEQ * DINNER + h * HEADDIM + p;

    unsigned long long s2[8];
    #pragma unroll
    for (int j = 0; j < 8; j++) s2[j] = 0ull;

    const int rrow = tid >> 4;
    const int rc   = (tid & 15) << 2;
    const bool hasdt = tid < CH;
    const size_t xoff = (size_t)h * HEADDIM + rc;
    const size_t boff = (size_t)DINNER + rc;
    const size_t coff = (size_t)DINNER + DSTATE + rc;

    float4 rx, rB, rC; float rdt = 0.f;
    {
        const float* rowp = base + (size_t)rrow * CONVDIM;
        rx = *(const float4*)(rowp + xoff);
        rB = *(const float4*)(rowp + boff);
        rC = *(const float4*)(rowp + coff);
        if (hasdt) rdt = dtb[(size_t)tid * NHEADS];
    }
    *(float4*)&sx[0][rrow][rc] = rx;
    *(float4*)&sB[0][rrow][rc] = rB;
    *(float4*)&sC[0][rrow][rc] = rC;
    if (hasdt) { sdt[0][tid] = rdt; sdA[0][tid] = expf(rdt * Ac); }
    __syncthreads();

    const int nch = SEQ / CH;
    for (int c = 0; c < nch; c++) {
        const int cur = c & 1;
        if (c + 1 < nch) {
            const int t0 = (c + 1) * CH;
            const float* rowp = base + (size_t)(t0 + rrow) * CONVDIM;
            rx = *(const float4*)(rowp + xoff);
            rB = *(const float4*)(rowp + boff);
            rC = *(const float4*)(rowp + coff);
            if (hasdt) rdt = dtb[(size_t)(t0 + tid) * NHEADS];
        }
        for (int s = 0; s < CH; s++) {
            const float dtv = sdt[cur][s];
            const float dA  = sdA[cur][s];
            const float xv  = sx[cur][s][p];
            const float u   = dtv * xv;
            unsigned long long u2 = pk2(u, u), dA2 = pk2(dA, dA), acc2 = 0ull;
            #pragma unroll
            for (int j = 0; j < 8; j++) {
                float2 Bv = *(const float2*)&sB[cur][s][q * 16 + j * 2];
                float2 Cv = *(const float2*)&sC[cur][s][q * 16 + j * 2];
                unsigned long long t2 = mul2(u2, pk2(Bv.x, Bv.y));
                fma2(t2, s2[j], dA2);
                s2[j] = t2;
                fma2(acc2, t2, pk2(Cv.x, Cv.y));
            }
            float2 af = upk(acc2);
            float acc = af.x + af.y;
            acc += __shfl_xor_sync(0xffffffffu, acc, 1);
            acc += __shfl_xor_sync(0xffffffffu, acc, 2);
            if (q == 0) yb[(size_t)(c * CH + s) * DINNER] = acc + Dv * xv;
        }
        if (c + 1 < nch) {
            const int nx = (c + 1) & 1;
            *(float4*)&sx[nx][rrow][rc] = rx;
            *(float4*)&sB[nx][rrow][rc] = rB;
            *(float4*)&sC[nx][rrow][rc] = rC;
            if (hasdt) { sdt[nx][tid] = rdt; sdA[nx][tid] = expf(rdt * Ac); }
        }
        __syncthreads();
    }
}

// ---------------- gate (y * silu(z)) + RMSNorm, writes fp16 hi/lo planes ----------------
__global__ __launch_bounds__(256) void gate_rms_split_kernel(
    const float* __restrict__ y, const float* __restrict__ zx,
    const float* __restrict__ nw, __half* __restrict__ oh, __half* __restrict__ ol)
{
    int row = blockIdx.x, tid = threadIdx.x;
    const float4* yr = (const float4*)(y  + (size_t)row * DINNER);
    const float4* zr = (const float4*)(zx + (size_t)row * DINPROJ);
    float4 v[2]; float ss = 0.f;
    #pragma unroll
    for (int i = 0; i < 2; i++) {
        int idx = tid + i * 256;
        float4 yv = yr[idx], zv = zr[idx];
        float4 r;
        r.x = yv.x * (zv.x / (1.f + __expf(-zv.x)));
        r.y = yv.y * (zv.y / (1.f + __expf(-zv.y)));
        r.z = yv.z * (zv.z / (1.f + __expf(-zv.z)));
        r.w = yv.w * (zv.w / (1.f + __expf(-zv.w)));
        ss += r.x*r.x + r.y*r.y + r.z*r.z + r.w*r.w;
        v[i] = r;
    }
    float tot = block_sum256(ss);
    float sc = rsqrtf(tot * (1.f / DINNER) + EPS);
    const float4* nwv = (const float4*)nw;
    uint2* ohp = (uint2*)(oh + (size_t)row * DINNER);
    uint2* olp = (uint2*)(ol + (size_t)row * DINNER);
    #pragma unroll
    for (int i = 0; i < 2; i++) {
        int idx = tid + i * 256;
        float4 w = nwv[idx];
        float4 r = v[i];
        float4 o = {r.x*sc*w.x, r.y*sc*w.y, r.z*sc*w.z, r.w*sc*w.w};
        uint2 h, l;
        cvt_split_h(o, h, l);
        ohp[idx] = h;
        olp[idx] = l;
    }
}

// ---------------- launch ----------------
extern "C" void kernel_launch(void* const* d_in, const int* in_sizes, int n_in,
                              void* d_out, int out_size) {
    const float* x        = (const float*)d_in[0];
    const float* ln1_w    = (const float*)d_in[1];
    const float* ln1_b    = (const float*)d_in[2];
    const float* in_proj  = (const float*)d_in[3];
    const float* conv_w   = (const float*)d_in[4];
    const float* conv_b   = (const float*)d_in[5];
    const float* dt_bias  = (const float*)d_in[6];
    const float* A_log    = (const float*)d_in[7];
    const float* Dp       = (const float*)d_in[8];
    const float* norm_w   = (const float*)d_in[9];
    const float* out_proj = (const float*)d_in[10];
    const float* ln2_w    = (const float*)d_in[11];
    const float* ln2_b    = (const float*)d_in[12];
    const float* mlp_w1   = (const float*)d_in[13];
    const float* mlp_b1   = (const float*)d_in[14];
    const float* mlp_w2   = (const float*)d_in[15];
    const float* mlp_b2   = (const float*)d_in[16];
    float* out = (float*)d_out;

    float *zx, *xbc, *dt, *y, *x2;
    cudaGetSymbolAddress((void**)&zx,  g_zx);
    cudaGetSymbolAddress((void**)&xbc, g_xbc);
    cudaGetSymbolAddress((void**)&dt,  g_dt);
    cudaGetSymbolAddress((void**)&y,   g_y);
    cudaGetSymbolAddress((void**)&x2,  g_x2);
    __half *h1h,*h1l,*ynh,*ynl,*h2h,*h2l,*mdh,*mdl;
    __half *wi,*wo,*w1,*w2;
    cudaGetSymbolAddress((void**)&h1h, g_h1h); cudaGetSymbolAddress((void**)&h1l, g_h1l);
    cudaGetSymbolAddress((void**)&ynh, g_ynh); cudaGetSymbolAddress((void**)&ynl, g_ynl);
    cudaGetSymbolAddress((void**)&h2h, g_h2h); cudaGetSymbolAddress((void**)&h2l, g_h2l);
    cudaGetSymbolAddress((void**)&mdh, g_mdh); cudaGetSymbolAddress((void**)&mdl, g_mdl);
    cudaGetSymbolAddress((void**)&wi,  g_wi);  cudaGetSymbolAddress((void**)&wo,  g_wo);
    cudaGetSymbolAddress((void**)&w1,  g_w1);  cudaGetSymbolAddress((void**)&w2,  g_w2);

    cudaFuncSetAttribute(gemm_mma<0,0>, cudaFuncAttributeMaxDynamicSharedMemorySize, GEMM_SMEM);
    cudaFuncSetAttribute(gemm_mma<1,1>, cudaFuncAttributeMaxDynamicSharedMemorySize, GEMM_SMEM);
    cudaFuncSetAttribute(gemm_mma<2,0>, cudaFuncAttributeMaxDynamicSharedMemorySize, GEMM_SMEM);
    cudaFuncSetAttribute(gemm_mma<3,0>, cudaFuncAttributeMaxDynamicSharedMemorySize, GEMM_SMEM);

    // 0. weight converts (once per launch)
    wcvt_kernel<<<(DINPROJ*DMODEL/4 + 255)/256, 256>>>(in_proj,  wi, DINPROJ*DMODEL/4);
    wcvt_kernel<<<(DMODEL*DINNER/4 + 255)/256, 256>>>(out_proj, wo, DMODEL*DINNER/4);
    wcvt_kernel<<<(DMLP*DMODEL/4 + 255)/256, 256>>>(mlp_w1,   w1, DMLP*DMODEL/4);
    wcvt_kernel<<<(DMODEL*DMLP/4 + 255)/256, 256>>>(mlp_w2,   w2, DMODEL*DMLP/4);

    // 1. LN1 -> h1 planes
    ln_split_kernel<<<NTOK, 256>>>(x, ln1_w, ln1_b, h1h, h1l);
    // 2. in_proj -> zx (fp32)
    gemm_mma<0,0><<<dim3((DINPROJ + 127) / 128, NTOK / 128), 256, GEMM_SMEM>>>(
        h1h, h1l, wi, zx, nullptr, nullptr, NTOK, DINPROJ, DMODEL, nullptr, nullptr);
    // 3. dt
    dt_kernel<<<(NTOK * NHEADS) / 256, 256>>>(zx, dt_bias, dt);
    // 4. conv + silu
    conv_kernel<<<dim3((CONVDIM + 255) / 256, NTOK), 256>>>(zx, conv_w, conv_b, xbc);
    // 5. scan
    scan_kernel<<<BATCH * NHEADS, 256>>>(xbc, dt, A_log, Dp, y);
    // 6. gate + rmsnorm -> yn planes
    gate_rms_split_kernel<<<NTOK, 256>>>(y, zx, norm_w, ynh, ynl);
    // 7. out_proj + residual(x) -> x2 (fp32)
    gemm_mma<2,0><<<dim3(DMODEL / 128, NTOK / 128), 256, GEMM_SMEM>>>(
        ynh, ynl, wo, x2, nullptr, nullptr, NTOK, DMODEL, DINNER, nullptr, x);
    // 8. LN2 -> h2 planes
    ln_split_kernel<<<NTOK, 256>>>(x2, ln2_w, ln2_b, h2h, h2l);
    // 9. mlp1 + bias + gelu -> mid planes
    gemm_mma<1,1><<<dim3(DMLP / 128, NTOK / 128), 256, GEMM_SMEM>>>(
        h2h, h2l, w1, nullptr, mdh, mdl, NTOK, DMLP, DMODEL, mlp_b1, nullptr);
    // 10. mlp2 + bias + residual(x2) -> out (fp32)
    gemm_mma<3,0><<<dim3(DMODEL / 128, NTOK / 128), 256, GEMM_SMEM>>>(
        mdh, mdl, w2, out, nullptr, nullptr, NTOK, DMODEL, DMLP, mlp_b2, x2);
}

// round 14
// speedup vs baseline: 1.2539x; 1.2539x over previous
#include <cuda_runtime.h>
#include <cuda_bf16.h>
#include <math.h>
#include <stdint.h>

// ---------------- Problem constants ----------------
#define BATCH   2
#define SEQ     2048
#define NTOK    (BATCH*SEQ)          // 4096
#define DMODEL  1024
#define DINNER  2048
#define NHEADS  32
#define HEADDIM 64
#define DSTATE  64
#define DCONV   4
#define CONVDIM 2176                 // DINNER + 2*DSTATE
#define DINPROJ 4256                 // 2*DINNER + 2*DSTATE + NHEADS
#define DMLP    4096
#define EPS     1e-5f

// ---------------- Scratch (device globals; no allocation allowed) ----------------
__device__ float g_zx [NTOK*DINPROJ];
__device__ float g_xbc[NTOK*CONVDIM];
__device__ float g_dt [NTOK*NHEADS];
__device__ float g_y  [NTOK*DINNER];
__device__ float g_x2 [NTOK*DMODEL];
// activation bf16 hi/lo planes (GEMM A operands)
__device__ __nv_bfloat16 g_h1h[NTOK*DMODEL],  g_h1l[NTOK*DMODEL];
__device__ __nv_bfloat16 g_ynh[NTOK*DINNER],  g_ynl[NTOK*DINNER];
__device__ __nv_bfloat16 g_h2h[NTOK*DMODEL],  g_h2l[NTOK*DMODEL];
__device__ __nv_bfloat16 g_mdh[NTOK*DMLP],    g_mdl[NTOK*DMLP];
// weight bf16 hi/lo planes (GEMM B operands)
__device__ __nv_bfloat16 g_wih[DINPROJ*DMODEL], g_wil[DINPROJ*DMODEL];
__device__ __nv_bfloat16 g_woh[DMODEL*DINNER],  g_wol[DMODEL*DINNER];
__device__ __nv_bfloat16 g_w1h[DMLP*DMODEL],    g_w1l[DMLP*DMODEL];
__device__ __nv_bfloat16 g_w2h[DMODEL*DMLP],    g_w2l[DMODEL*DMLP];

// ---------------- f32x2 packed helpers (scan) ----------------
__device__ __forceinline__ unsigned long long pk2(float x, float y) {
    unsigned long long r;
    asm("mov.b64 %0, {%1, %2};" : "=l"(r) : "f"(x), "f"(y));
    return r;
}
__device__ __forceinline__ float2 upk(unsigned long long v) {
    float2 f;
    asm("mov.b64 {%0, %1}, %2;" : "=f"(f.x), "=f"(f.y) : "l"(v));
    return f;
}
__device__ __forceinline__ void fma2(unsigned long long &d, unsigned long long a, unsigned long long b) {
    asm("fma.rn.f32x2 %0, %1, %2, %0;" : "+l"(d) : "l"(a), "l"(b));
}
__device__ __forceinline__ unsigned long long mul2(unsigned long long a, unsigned long long b) {
    unsigned long long r;
    asm("mul.rn.f32x2 %0, %1, %2;" : "=l"(r) : "l"(a), "l"(b));
    return r;
}

// ---------------- mma.sync helpers (portable sm_80+ PTX) ----------------
__device__ __forceinline__ uint32_t smem_u32(const void* p) {
    uint32_t a;
    asm("{ .reg .u64 t; cvta.to.shared.u64 t, %1; cvt.u32.u64 %0, t; }" : "=r"(a) : "l"(p));
    return a;
}
__device__ __forceinline__ void ldsm_x4(uint32_t &r0, uint32_t &r1, uint32_t &r2, uint32_t &r3,
                                        uint32_t addr) {
    asm volatile("ldmatrix.sync.aligned.m8n8.x4.shared.b16 {%0,%1,%2,%3}, [%4];"
                 : "=r"(r0), "=r"(r1), "=r"(r2), "=r"(r3) : "r"(addr));
}
__device__ __forceinline__ void mma_bf16(float* c, const uint32_t* a, const uint32_t* b) {
    asm volatile(
        "mma.sync.aligned.m16n8k16.row.col.f32.bf16.bf16.f32 "
        "{%0,%1,%2,%3}, {%4,%5,%6,%7}, {%8,%9}, {%0,%1,%2,%3};"
        : "+f"(c[0]), "+f"(c[1]), "+f"(c[2]), "+f"(c[3])
        : "r"(a[0]), "r"(a[1]), "r"(a[2]), "r"(a[3]), "r"(b[0]), "r"(b[1]));
}

// ---------------- bf16 hi/lo split ----------------
__device__ __forceinline__ void cvt_split(float4 v, uint2 &hi, uint2 &lo) {
    __nv_bfloat162 h0 = __float22bfloat162_rn(make_float2(v.x, v.y));
    __nv_bfloat162 h1 = __float22bfloat162_rn(make_float2(v.z, v.w));
    float2 f0 = __bfloat1622float2(h0);
    float2 f1 = __bfloat1622float2(h1);
    __nv_bfloat162 l0 = __float22bfloat162_rn(make_float2(v.x - f0.x, v.y - f0.y));
    __nv_bfloat162 l1 = __float22bfloat162_rn(make_float2(v.z - f1.x, v.w - f1.y));
    hi.x = *(uint32_t*)&h0; hi.y = *(uint32_t*)&h1;
    lo.x = *(uint32_t*)&l0; lo.y = *(uint32_t*)&l1;
}

// ---------------- weight split: fp32 -> hi/lo bf16 planes ----------------
__global__ __launch_bounds__(256) void split_kernel(
    const float* __restrict__ src, __nv_bfloat16* __restrict__ hi,
    __nv_bfloat16* __restrict__ lo, int n4)
{
    int i = blockIdx.x * 256 + threadIdx.x;
    if (i >= n4) return;
    float4 v = ((const float4*)src)[i];
    uint2 h, l;
    cvt_split(v, h, l);
    ((uint2*)hi)[i] = h;
    ((uint2*)lo)[i] = l;
}

// ---------------- block reduction (256 threads) ----------------
__device__ __forceinline__ float block_sum256(float v) {
    __shared__ float sb[8];
    #pragma unroll
    for (int o = 16; o; o >>= 1) v += __shfl_xor_sync(0xffffffffu, v, o);
    int w = threadIdx.x >> 5;
    if ((threadIdx.x & 31) == 0) sb[w] = v;
    __syncthreads();
    if (threadIdx.x == 0) {
        float t = 0.f;
        #pragma unroll
        for (int i = 0; i < 8; i++) t += sb[i];
        sb[0] = t;
    }
    __syncthreads();
    float r = sb[0];
    __syncthreads();
    return r;
}

// ---------------- LayerNorm: rows of 1024, writes hi/lo bf16 planes ----------------
__global__ __launch_bounds__(256) void ln_split_kernel(
    const float* __restrict__ x, const float* __restrict__ w,
    const float* __restrict__ b, __nv_bfloat16* __restrict__ oh,
    __nv_bfloat16* __restrict__ ol)
{
    int row = blockIdx.x, tid = threadIdx.x;
    const float4* xr = (const float4*)(x + (size_t)row * DMODEL);
    float4 v = xr[tid];
    float mu = block_sum256(v.x + v.y + v.z + v.w) * (1.f / DMODEL);
    float4 d = {v.x - mu, v.y - mu, v.z - mu, v.w - mu};
    float var = block_sum256(d.x*d.x + d.y*d.y + d.z*d.z + d.w*d.w) * (1.f / DMODEL);
    float rs = rsqrtf(var + EPS);
    float4 wv = ((const float4*)w)[tid];
    float4 bv = ((const float4*)b)[tid];
    float4 o = {d.x*rs*wv.x + bv.x, d.y*rs*wv.y + bv.y, d.z*rs*wv.z + bv.z, d.w*rs*wv.w + bv.w};
    uint2 h, l;
    cvt_split(o, h, l);
    ((uint2*)(oh + (size_t)row * DMODEL))[tid] = h;
    ((uint2*)(ol + (size_t)row * DMODEL))[tid] = l;
}

// ---------------- GEMM via mma.sync: C[M,N] = A[M,K] @ B[N,K]^T (+ epilogue) ----------------
// Tile 128x64, 2 CTAs/SM target. A, B bf16 hi/lo planes.
// 3-term: Ah*Bh + Ah*Bl + Al*Bh (fp32 accumulate).
// EPI: 0 = none, 1 = bias+gelu(exact), 2 = +res, 3 = +bias+res
// OUTP: 0 = fp32 C, 1 = bf16 hi/lo planes (Chi/Clo)
template<int EPI>
__device__ __forceinline__ float epi_f(float v, int gn, const float* __restrict__ bias,
                                       const float* __restrict__ rrow) {
    if (EPI == 1) { v += bias[gn]; return 0.5f * v * (1.f + erff(v * 0.70710678118654752f)); }
    if (EPI == 2) return v + rrow[gn];
    if (EPI == 3) return v + bias[gn] + rrow[gn];
    return v;
}

#define ROWB    80                   // bytes per SMEM row: 32 bf16 data + 8 pad
#define PLANE_A (128*ROWB)           // 10240 B
#define PLANE_B (64*ROWB)            // 5120 B
#define STAGEB  (2*PLANE_A + 2*PLANE_B)  // 30720 B: [Ah][Al][Bh][Bl]
#define GEMM_SMEM (2*STAGEB)         // 61440 B

template<int EPI, int OUTP>
__global__ __launch_bounds__(256, 2) void gemm_mma(
    const __nv_bfloat16* __restrict__ Ahp, const __nv_bfloat16* __restrict__ Alp,
    const __nv_bfloat16* __restrict__ Bhp, const __nv_bfloat16* __restrict__ Blp,
    float* __restrict__ C, __nv_bfloat16* __restrict__ Chi, __nv_bfloat16* __restrict__ Clo,
    int M, int N, int K, const float* __restrict__ bias, const float* __restrict__ res)
{
    extern __shared__ char smem[];
    const int tid = threadIdx.x;
    const int m0 = blockIdx.y * 128, n0 = blockIdx.x * 64;
    const int warp = tid >> 5, lane = tid & 31;
    const int wm = (warp & 3) * 32;      // warp grid: 4 along M
    const int wn = (warp >> 2) * 32;     // 2 along N

    // loader: thread covers 8 bf16 (16B) at k-offset (tid&3)*8
    // A rows rq and rq+64 (2 loads/plane); B row rq (1 load/plane)
    const int rq = tid >> 2;             // 0..63
    const int kc = (tid & 3) * 8;
    const __nv_bfloat16* Ah0 = Ahp + (size_t)(m0 + rq) * K + kc;
    const __nv_bfloat16* Al0 = Alp + (size_t)(m0 + rq) * K + kc;
    const __nv_bfloat16* Bh0 = Bhp + (size_t)(n0 + rq) * K + kc;
    const __nv_bfloat16* Bl0 = Blp + (size_t)(n0 + rq) * K + kc;
    const size_t rstep = (size_t)64 * K;
    const bool bok = (n0 + rq) < N;
    const uint32_t wb = (uint32_t)rq * ROWB + (tid & 3) * 16;

    const uint32_t sbase = smem_u32(smem);

    float acc[2][4][4];
    #pragma unroll
    for (int mt = 0; mt < 2; mt++)
        #pragma unroll
        for (int nt = 0; nt < 4; nt++)
            #pragma unroll
            for (int r = 0; r < 4; r++) acc[mt][nt][r] = 0.f;

    const uint4 z4 = {0u, 0u, 0u, 0u};
    uint4 vah0, vah1, val0, val1, vbh0, vbl0;

    // prologue: chunk 0 -> stage 0
    vah0 = *(const uint4*)(Ah0);
    vah1 = *(const uint4*)(Ah0 + rstep);
    val0 = *(const uint4*)(Al0);
    val1 = *(const uint4*)(Al0 + rstep);
    vbh0 = bok ? *(const uint4*)(Bh0) : z4;
    vbl0 = bok ? *(const uint4*)(Bl0) : z4;
    {
        char* st = smem;
        *(uint4*)(st + 0*PLANE_A + wb)           = vah0;
        *(uint4*)(st + 0*PLANE_A + wb + 64*ROWB) = vah1;
        *(uint4*)(st + 1*PLANE_A + wb)           = val0;
        *(uint4*)(st + 1*PLANE_A + wb + 64*ROWB) = val1;
        *(uint4*)(st + 2*PLANE_A + wb)           = vbh0;
        *(uint4*)(st + 2*PLANE_A + PLANE_B + wb) = vbl0;
    }
    __syncthreads();

    const int nch = K >> 5;   // K/32
    for (int c = 0; c < nch; c++) {
        const int cur = c & 1;
        const uint32_t sb = sbase + cur * STAGEB;

        if (c + 1 < nch) {
            const size_t kf = (size_t)(c + 1) * 32;
            vah0 = *(const uint4*)(Ah0 + kf);
            vah1 = *(const uint4*)(Ah0 + kf + rstep);
            val0 = *(const uint4*)(Al0 + kf);
            val1 = *(const uint4*)(Al0 + kf + rstep);
            vbh0 = bok ? *(const uint4*)(Bh0 + kf) : z4;
            vbl0 = bok ? *(const uint4*)(Bl0 + kf) : z4;
        }

        // compute: 2 k16 steps
        #pragma unroll
        for (int ks = 0; ks < 2; ks++) {
            const uint32_t kb = ks * 32;
            uint32_t ah[2][4], al[2][4], bh[4][2], bl[4][2];
            #pragma unroll
            for (int mt = 0; mt < 2; mt++) {
                uint32_t ar = sb + (uint32_t)(wm + mt * 16 + (lane & 15)) * ROWB
                            + kb + ((lane >> 4) << 4);
                ldsm_x4(ah[mt][0], ah[mt][1], ah[mt][2], ah[mt][3], ar);
                ldsm_x4(al[mt][0], al[mt][1], al[mt][2], al[mt][3], ar + PLANE_A);
            }
            const int g = lane >> 3;
            #pragma unroll
            for (int pr = 0; pr < 2; pr++) {
                uint32_t br = sb + 2*PLANE_A
                            + (uint32_t)(wn + pr * 16 + ((g >> 1) << 3) + (lane & 7)) * ROWB
                            + kb + ((g & 1) << 4);
                uint32_t r0, r1, r2, r3;
                ldsm_x4(r0, r1, r2, r3, br);
                bh[2*pr][0] = r0; bh[2*pr][1] = r1; bh[2*pr+1][0] = r2; bh[2*pr+1][1] = r3;
                ldsm_x4(r0, r1, r2, r3, br + PLANE_B);
                bl[2*pr][0] = r0; bl[2*pr][1] = r1; bl[2*pr+1][0] = r2; bl[2*pr+1][1] = r3;
            }
            #pragma unroll
            for (int mt = 0; mt < 2; mt++)
                #pragma unroll
                for (int nt = 0; nt < 4; nt++) {
                    mma_bf16(acc[mt][nt], ah[mt], bh[nt]);
                    mma_bf16(acc[mt][nt], ah[mt], bl[nt]);
                    mma_bf16(acc[mt][nt], al[mt], bh[nt]);
                }
        }

        if (c + 1 < nch) {
            char* st = smem + (cur ^ 1) * STAGEB;
            *(uint4*)(st + 0*PLANE_A + wb)           = vah0;
            *(uint4*)(st + 0*PLANE_A + wb + 64*ROWB) = vah1;
            *(uint4*)(st + 1*PLANE_A + wb)           = val0;
            *(uint4*)(st + 1*PLANE_A + wb + 64*ROWB) = val1;
            *(uint4*)(st + 2*PLANE_A + wb)           = vbh0;
            *(uint4*)(st + 2*PLANE_A + PLANE_B + wb) = vbl0;
        }
        __syncthreads();
    }

    // epilogue: frag c0=(r, col) c1=(r, col+1) c2=(r+8, col) c3=(r+8, col+1)
    #pragma unroll
    for (int mt = 0; mt < 2; mt++) {
        const int gr = m0 + wm + mt * 16 + (lane >> 2);
        const float* R0 = (EPI >= 2) ? (res + (size_t)gr * N) : (const float*)0;
        const float* R1 = (EPI >= 2) ? (res + (size_t)(gr + 8) * N) : (const float*)0;
        #pragma unroll
        for (int nt = 0; nt < 4; nt++) {
            const int gc = n0 + wn + nt * 8 + (lane & 3) * 2;
            if (gc < N) {
                float2 v0 = { epi_f<EPI>(acc[mt][nt][0], gc,     bias, R0),
                              epi_f<EPI>(acc[mt][nt][1], gc + 1, bias, R0) };
                float2 v1 = { epi_f<EPI>(acc[mt][nt][2], gc,     bias, R1),
                              epi_f<EPI>(acc[mt][nt][3], gc + 1, bias, R1) };
                if (OUTP == 0) {
                    *(float2*)(C + (size_t)gr * N + gc) = v0;
                    *(float2*)(C + (size_t)(gr + 8) * N + gc) = v1;
                } else {
                    __nv_bfloat162 h0 = __float22bfloat162_rn(v0);
                    float2 f0 = __bfloat1622float2(h0);
                    __nv_bfloat162 l0 = __float22bfloat162_rn(make_float2(v0.x - f0.x, v0.y - f0.y));
                    __nv_bfloat162 h1 = __float22bfloat162_rn(v1);
                    float2 f1 = __bfloat1622float2(h1);
                    __nv_bfloat162 l1 = __float22bfloat162_rn(make_float2(v1.x - f1.x, v1.y - f1.y));
                    *(__nv_bfloat162*)(Chi + (size_t)gr * N + gc) = h0;
                    *(__nv_bfloat162*)(Clo + (size_t)gr * N + gc) = l0;
                    *(__nv_bfloat162*)(Chi + (size_t)(gr + 8) * N + gc) = h1;
                    *(__nv_bfloat162*)(Clo + (size_t)(gr + 8) * N + gc) = l1;
                }
            }
        }
    }
}

// ---------------- dt = softplus(zx[..., 4224:4256] + dt_bias) ----------------
__global__ __launch_bounds__(256) void dt_kernel(
    const float* __restrict__ zx, const float* __restrict__ dt_bias, float* __restrict__ dt)
{
    int idx = blockIdx.x * 256 + threadIdx.x;  // NTOK*32
    int t = idx >> 5, h = idx & 31;
    float v = zx[(size_t)t * DINPROJ + (DINNER + CONVDIM) + h] + dt_bias[h];
    dt[idx] = (v > 20.f) ? v : log1pf(__expf(v));
}

// ---------------- causal depthwise conv(4) + silu ----------------
__global__ __launch_bounds__(256) void conv_kernel(
    const float* __restrict__ zx, const float* __restrict__ cw,
    const float* __restrict__ cb, float* __restrict__ xbc)
{
    int c = blockIdx.x * 256 + threadIdx.x;
    if (c >= CONVDIM) return;
    int t = blockIdx.y;
    int b = t >> 11, tl = t & 2047;
    float acc = cb[c];
    const float* src = zx + (size_t)b * SEQ * DINPROJ + DINNER + c;
    #pragma unroll
    for (int k = 0; k < DCONV; k++) {
        int ts = tl - 3 + k;
        if (ts >= 0) acc += src[(size_t)ts * DINPROJ] * cw[c * DCONV + k];
    }
    float s = acc / (1.f + __expf(-acc));
    xbc[(size_t)t * CONVDIM + c] = s;
}

// ---------------- SSM sequential scan ----------------
__global__ __launch_bounds__(256) void scan_kernel(
    const float* __restrict__ xbc, const float* __restrict__ dtp,
    const float* __restrict__ A_log, const float* __restrict__ Dp,
    float* __restrict__ y)
{
    const int CH = 16;
    __shared__ float sx[2][CH][64], sB[2][CH][64], sC[2][CH][64];
    __shared__ float sdt[2][CH], sdA[2][CH];
    const int bh = blockIdx.x, b = bh >> 5, h = bh & 31;
    const int tid = threadIdx.x, p = tid >> 2, q = tid & 3;
    const float Ac = -expf(A_log[h]);
    const float Dv = Dp[h];
    const float* base = xbc + (size_t)b * SEQ * CONVDIM;
    const float* dtb  = dtp + (size_t)b * SEQ * NHEADS + h;
    float* yb = y + (size_t)b * SEQ * DINNER + h * HEADDIM + p;

    unsigned long long s2[8];
    #pragma unroll
    for (int j = 0; j < 8; j++) s2[j] = 0ull;

    const int rrow = tid >> 4;
    const int rc   = (tid & 15) << 2;
    const bool hasdt = tid < CH;
    const size_t xoff = (size_t)h * HEADDIM + rc;
    const size_t boff = (size_t)DINNER + rc;
    const size_t coff = (size_t)DINNER + DSTATE + rc;

    float4 rx, rB, rC; float rdt = 0.f;
    {
        const float* rowp = base + (size_t)rrow * CONVDIM;
        rx = *(const float4*)(rowp + xoff);
        rB = *(const float4*)(rowp + boff);
        rC = *(const float4*)(rowp + coff);
        if (hasdt) rdt = dtb[(size_t)tid * NHEADS];
    }
    *(float4*)&sx[0][rrow][rc] = rx;
    *(float4*)&sB[0][rrow][rc] = rB;
    *(float4*)&sC[0][rrow][rc] = rC;
    if (hasdt) { sdt[0][tid] = rdt; sdA[0][tid] = expf(rdt * Ac); }
    __syncthreads();

    const int nch = SEQ / CH;
    for (int c = 0; c < nch; c++) {
        const int cur = c & 1;
        if (c + 1 < nch) {
            const int t0 = (c + 1) * CH;
            const float* rowp = base + (size_t)(t0 + rrow) * CONVDIM;
            rx = *(const float4*)(rowp + xoff);
            rB = *(const float4*)(rowp + boff);
            rC = *(const float4*)(rowp + coff);
            if (hasdt) rdt = dtb[(size_t)(t0 + tid) * NHEADS];
        }
        for (int s = 0; s < CH; s++) {
            const float dtv = sdt[cur][s];
            const float dA  = sdA[cur][s];
            const float xv  = sx[cur][s][p];
            const float u   = dtv * xv;
            unsigned long long u2 = pk2(u, u), dA2 = pk2(dA, dA), acc2 = 0ull;
            #pragma unroll
            for (int j = 0; j < 8; j++) {
                float2 Bv = *(const float2*)&sB[cur][s][q * 16 + j * 2];
                float2 Cv = *(const float2*)&sC[cur][s][q * 16 + j * 2];
                unsigned long long t2 = mul2(u2, pk2(Bv.x, Bv.y));
                fma2(t2, s2[j], dA2);
                s2[j] = t2;
                fma2(acc2, t2, pk2(Cv.x, Cv.y));
            }
            float2 af = upk(acc2);
            float acc = af.x + af.y;
            acc += __shfl_xor_sync(0xffffffffu, acc, 1);
            acc += __shfl_xor_sync(0xffffffffu, acc, 2);
            if (q == 0) yb[(size_t)(c * CH + s) * DINNER] = acc + Dv * xv;
        }
        if (c + 1 < nch) {
            const int nx = (c + 1) & 1;
            *(float4*)&sx[nx][rrow][rc] = rx;
            *(float4*)&sB[nx][rrow][rc] = rB;
            *(float4*)&sC[nx][rrow][rc] = rC;
            if (hasdt) { sdt[nx][tid] = rdt; sdA[nx][tid] = expf(rdt * Ac); }
        }
        __syncthreads();
    }
}

// ---------------- gate (y * silu(z)) + RMSNorm, writes hi/lo planes ----------------
__global__ __launch_bounds__(256) void gate_rms_split_kernel(
    const float* __restrict__ y, const float* __restrict__ zx,
    const float* __restrict__ nw, __nv_bfloat16* __restrict__ oh,
    __nv_bfloat16* __restrict__ ol)
{
    int row = blockIdx.x, tid = threadIdx.x;
    const float4* yr = (const float4*)(y  + (size_t)row * DINNER);
    const float4* zr = (const float4*)(zx + (size_t)row * DINPROJ);
    float4 v[2]; float ss = 0.f;
    #pragma unroll
    for (int i = 0; i < 2; i++) {
        int idx = tid + i * 256;
        float4 yv = yr[idx], zv = zr[idx];
        float4 r;
        r.x = yv.x * (zv.x / (1.f + __expf(-zv.x)));
        r.y = yv.y * (zv.y / (1.f + __expf(-zv.y)));
        r.z = yv.z * (zv.z / (1.f + __expf(-zv.z)));
        r.w = yv.w * (zv.w / (1.f + __expf(-zv.w)));
        ss += r.x*r.x + r.y*r.y + r.z*r.z + r.w*r.w;
        v[i] = r;
    }
    float tot = block_sum256(ss);
    float sc = rsqrtf(tot * (1.f / DINNER) + EPS);
    const float4* nwv = (const float4*)nw;
    uint2* ohp = (uint2*)(oh + (size_t)row * DINNER);
    uint2* olp = (uint2*)(ol + (size_t)row * DINNER);
    #pragma unroll
    for (int i = 0; i < 2; i++) {
        int idx = tid + i * 256;
        float4 w = nwv[idx];
        float4 r = v[i];
        float4 o = {r.x*sc*w.x, r.y*sc*w.y, r.z*sc*w.z, r.w*sc*w.w};
        uint2 h, l;
        cvt_split(o, h, l);
        ohp[idx] = h;
        olp[idx] = l;
    }
}

// ---------------- launch ----------------
extern "C" void kernel_launch(void* const* d_in, const int* in_sizes, int n_in,
                              void* d_out, int out_size) {
    const float* x        = (const float*)d_in[0];
    const float* ln1_w    = (const float*)d_in[1];
    const float* ln1_b    = (const float*)d_in[2];
    const float* in_proj  = (const float*)d_in[3];
    const float* conv_w   = (const float*)d_in[4];
    const float* conv_b   = (const float*)d_in[5];
    const float* dt_bias  = (const float*)d_in[6];
    const float* A_log    = (const float*)d_in[7];
    const float* Dp       = (const float*)d_in[8];
    const float* norm_w   = (const float*)d_in[9];
    const float* out_proj = (const float*)d_in[10];
    const float* ln2_w    = (const float*)d_in[11];
    const float* ln2_b    = (const float*)d_in[12];
    const float* mlp_w1   = (const float*)d_in[13];
    const float* mlp_b1   = (const float*)d_in[14];
    const float* mlp_w2   = (const float*)d_in[15];
    const float* mlp_b2   = (const float*)d_in[16];
    float* out = (float*)d_out;

    float *zx, *xbc, *dt, *y, *x2;
    cudaGetSymbolAddress((void**)&zx,  g_zx);
    cudaGetSymbolAddress((void**)&xbc, g_xbc);
    cudaGetSymbolAddress((void**)&dt,  g_dt);
    cudaGetSymbolAddress((void**)&y,   g_y);
    cudaGetSymbolAddress((void**)&x2,  g_x2);
    __nv_bfloat16 *h1h,*h1l,*ynh,*ynl,*h2h,*h2l,*mdh,*mdl;
    __nv_bfloat16 *wih,*wil,*woh,*wol,*w1h,*w1l,*w2h,*w2l;
    cudaGetSymbolAddress((void**)&h1h, g_h1h); cudaGetSymbolAddress((void**)&h1l, g_h1l);
    cudaGetSymbolAddress((void**)&ynh, g_ynh); cudaGetSymbolAddress((void**)&ynl, g_ynl);
    cudaGetSymbolAddress((void**)&h2h, g_h2h); cudaGetSymbolAddress((void**)&h2l, g_h2l);
    cudaGetSymbolAddress((void**)&mdh, g_mdh); cudaGetSymbolAddress((void**)&mdl, g_mdl);
    cudaGetSymbolAddress((void**)&wih, g_wih); cudaGetSymbolAddress((void**)&wil, g_wil);
    cudaGetSymbolAddress((void**)&woh, g_woh); cudaGetSymbolAddress((void**)&wol, g_wol);
    cudaGetSymbolAddress((void**)&w1h, g_w1h); cudaGetSymbolAddress((void**)&w1l, g_w1l);
    cudaGetSymbolAddress((void**)&w2h, g_w2h); cudaGetSymbolAddress((void**)&w2l, g_w2l);

    cudaFuncSetAttribute(gemm_mma<0,0>, cudaFuncAttributeMaxDynamicSharedMemorySize, GEMM_SMEM);
    cudaFuncSetAttribute(gemm_mma<1,1>, cudaFuncAttributeMaxDynamicSharedMemorySize, GEMM_SMEM);
    cudaFuncSetAttribute(gemm_mma<2,0>, cudaFuncAttributeMaxDynamicSharedMemorySize, GEMM_SMEM);
    cudaFuncSetAttribute(gemm_mma<3,0>, cudaFuncAttributeMaxDynamicSharedMemorySize, GEMM_SMEM);

    // 0. weight splits (once per launch)
    split_kernel<<<(DINPROJ*DMODEL/4 + 255)/256, 256>>>(in_proj,  wih, wil, DINPROJ*DMODEL/4);
    split_kernel<<<(DMODEL*DINNER/4 + 255)/256, 256>>>(out_proj, woh, wol, DMODEL*DINNER/4);
    split_kernel<<<(DMLP*DMODEL/4 + 255)/256, 256>>>(mlp_w1,   w1h, w1l, DMLP*DMODEL/4);
    split_kernel<<<(DMODEL*DMLP/4 + 255)/256, 256>>>(mlp_w2,   w2h, w2l, DMODEL*DMLP/4);

    // 1. LN1 -> h1 planes
    ln_split_kernel<<<NTOK, 256>>>(x, ln1_w, ln1_b, h1h, h1l);
    // 2. in_proj -> zx (fp32)
    gemm_mma<0,0><<<dim3((DINPROJ + 63) / 64, NTOK / 128), 256, GEMM_SMEM>>>(
        h1h, h1l, wih, wil, zx, nullptr, nullptr, NTOK, DINPROJ, DMODEL, nullptr, nullptr);
    // 3. dt
    dt_kernel<<<(NTOK * NHEADS) / 256, 256>>>(zx, dt_bias, dt);
    // 4. conv + silu
    conv_kernel<<<dim3((CONVDIM + 255) / 256, NTOK), 256>>>(zx, conv_w, conv_b, xbc);
    // 5. scan
    scan_kernel<<<BATCH * NHEADS, 256>>>(xbc, dt, A_log, Dp, y);
    // 6. gate + rmsnorm -> yn planes
    gate_rms_split_kernel<<<NTOK, 256>>>(y, zx, norm_w, ynh, ynl);
    // 7. out_proj + residual(x) -> x2 (fp32)
    gemm_mma<2,0><<<dim3(DMODEL / 64, NTOK / 128), 256, GEMM_SMEM>>>(
        ynh, ynl, woh, wol, x2, nullptr, nullptr, NTOK, DMODEL, DINNER, nullptr, x);
    // 8. LN2 -> h2 planes
    ln_split_kernel<<<NTOK, 256>>>(x2, ln2_w, ln2_b, h2h, h2l);
    // 9. mlp1 + bias + gelu -> mid planes
    gemm_mma<1,1><<<dim3(DMLP / 64, NTOK / 128), 256, GEMM_SMEM>>>(
        h2h, h2l, w1h, w1l, nullptr, mdh, mdl, NTOK, DMLP, DMODEL, mlp_b1, nullptr);
    // 10. mlp2 + bias + residual(x2) -> out (fp32)
    gemm_mma<3,0><<<dim3(DMODEL / 64, NTOK / 128), 256, GEMM_SMEM>>>(
        mdh, mdl, w2h, w2l, out, nullptr, nullptr, NTOK, DMODEL, DMLP, mlp_b2, x2);
}

// round 15
// speedup vs baseline: 1.2697x; 1.0126x over previous
#include <cuda_runtime.h>
#include <cuda_bf16.h>
#include <math.h>
#include <stdint.h>

// ---------------- Problem constants ----------------
#define BATCH   2
#define SEQ     2048
#define NTOK    (BATCH*SEQ)          // 4096
#define DMODEL  1024
#define DINNER  2048
#define NHEADS  32
#define HEADDIM 64
#define DSTATE  64
#define DCONV   4
#define CONVDIM 2176                 // DINNER + 2*DSTATE
#define DINPROJ 4256                 // 2*DINNER + 2*DSTATE + NHEADS
#define DMLP    4096
#define EPS     1e-5f

// ---------------- Scratch (device globals; no allocation allowed) ----------------
__device__ float g_zx [NTOK*DINPROJ];
__device__ float g_xbc[NTOK*CONVDIM];
__device__ float g_dt [NTOK*NHEADS];
__device__ float g_y  [NTOK*DINNER];
__device__ float g_x2 [NTOK*DMODEL];
// activation bf16 hi/lo planes (GEMM A operands)
__device__ __nv_bfloat16 g_h1h[NTOK*DMODEL],  g_h1l[NTOK*DMODEL];
__device__ __nv_bfloat16 g_ynh[NTOK*DINNER],  g_ynl[NTOK*DINNER];
__device__ __nv_bfloat16 g_h2h[NTOK*DMODEL],  g_h2l[NTOK*DMODEL];
__device__ __nv_bfloat16 g_mdh[NTOK*DMLP],    g_mdl[NTOK*DMLP];
// weight bf16 hi/lo planes (GEMM B operands)
__device__ __nv_bfloat16 g_wih[DINPROJ*DMODEL], g_wil[DINPROJ*DMODEL];
__device__ __nv_bfloat16 g_woh[DMODEL*DINNER],  g_wol[DMODEL*DINNER];
__device__ __nv_bfloat16 g_w1h[DMLP*DMODEL],    g_w1l[DMLP*DMODEL];
__device__ __nv_bfloat16 g_w2h[DMODEL*DMLP],    g_w2l[DMODEL*DMLP];

// ---------------- f32x2 packed helpers (scan) ----------------
__device__ __forceinline__ unsigned long long pk2(float x, float y) {
    unsigned long long r;
    asm("mov.b64 %0, {%1, %2};" : "=l"(r) : "f"(x), "f"(y));
    return r;
}
__device__ __forceinline__ float2 upk(unsigned long long v) {
    float2 f;
    asm("mov.b64 {%0, %1}, %2;" : "=f"(f.x), "=f"(f.y) : "l"(v));
    return f;
}
__device__ __forceinline__ void fma2(unsigned long long &d, unsigned long long a, unsigned long long b) {
    asm("fma.rn.f32x2 %0, %1, %2, %0;" : "+l"(d) : "l"(a), "l"(b));
}
__device__ __forceinline__ unsigned long long mul2(unsigned long long a, unsigned long long b) {
    unsigned long long r;
    asm("mul.rn.f32x2 %0, %1, %2;" : "=l"(r) : "l"(a), "l"(b));
    return r;
}

// ---------------- mma.sync helpers (portable sm_80+ PTX) ----------------
__device__ __forceinline__ uint32_t smem_u32(const void* p) {
    uint32_t a;
    asm("{ .reg .u64 t; cvta.to.shared.u64 t, %1; cvt.u32.u64 %0, t; }" : "=r"(a) : "l"(p));
    return a;
}
__device__ __forceinline__ void ldsm_x4(uint32_t &r0, uint32_t &r1, uint32_t &r2, uint32_t &r3,
                                        uint32_t addr) {
    asm volatile("ldmatrix.sync.aligned.m8n8.x4.shared.b16 {%0,%1,%2,%3}, [%4];"
                 : "=r"(r0), "=r"(r1), "=r"(r2), "=r"(r3) : "r"(addr));
}
__device__ __forceinline__ void mma_bf16(float* c, const uint32_t* a, const uint32_t* b) {
    asm volatile(
        "mma.sync.aligned.m16n8k16.row.col.f32.bf16.bf16.f32 "
        "{%0,%1,%2,%3}, {%4,%5,%6,%7}, {%8,%9}, {%0,%1,%2,%3};"
        : "+f"(c[0]), "+f"(c[1]), "+f"(c[2]), "+f"(c[3])
        : "r"(a[0]), "r"(a[1]), "r"(a[2]), "r"(a[3]), "r"(b[0]), "r"(b[1]));
}
#define CPA16(dst, src, sz) \
    asm volatile("cp.async.cg.shared.global [%0], [%1], 16, %2;" \
                 :: "r"(dst), "l"(src), "r"(sz))
#define CP_COMMIT() asm volatile("cp.async.commit_group;" ::: "memory")

// ---------------- bf16 hi/lo split ----------------
__device__ __forceinline__ void cvt_split(float4 v, uint2 &hi, uint2 &lo) {
    __nv_bfloat162 h0 = __float22bfloat162_rn(make_float2(v.x, v.y));
    __nv_bfloat162 h1 = __float22bfloat162_rn(make_float2(v.z, v.w));
    float2 f0 = __bfloat1622float2(h0);
    float2 f1 = __bfloat1622float2(h1);
    __nv_bfloat162 l0 = __float22bfloat162_rn(make_float2(v.x - f0.x, v.y - f0.y));
    __nv_bfloat162 l1 = __float22bfloat162_rn(make_float2(v.z - f1.x, v.w - f1.y));
    hi.x = *(uint32_t*)&h0; hi.y = *(uint32_t*)&h1;
    lo.x = *(uint32_t*)&l0; lo.y = *(uint32_t*)&l1;
}

// ---------------- weight split: fp32 -> hi/lo bf16 planes ----------------
__global__ __launch_bounds__(256) void split_kernel(
    const float* __restrict__ src, __nv_bfloat16* __restrict__ hi,
    __nv_bfloat16* __restrict__ lo, int n4)
{
    int i = blockIdx.x * 256 + threadIdx.x;
    if (i >= n4) return;
    float4 v = ((const float4*)src)[i];
    uint2 h, l;
    cvt_split(v, h, l);
    ((uint2*)hi)[i] = h;
    ((uint2*)lo)[i] = l;
}

// ---------------- block reduction (256 threads) ----------------
__device__ __forceinline__ float block_sum256(float v) {
    __shared__ float sb[8];
    #pragma unroll
    for (int o = 16; o; o >>= 1) v += __shfl_xor_sync(0xffffffffu, v, o);
    int w = threadIdx.x >> 5;
    if ((threadIdx.x & 31) == 0) sb[w] = v;
    __syncthreads();
    if (threadIdx.x == 0) {
        float t = 0.f;
        #pragma unroll
        for (int i = 0; i < 8; i++) t += sb[i];
        sb[0] = t;
    }
    __syncthreads();
    float r = sb[0];
    __syncthreads();
    return r;
}

// ---------------- LayerNorm: rows of 1024, writes hi/lo bf16 planes ----------------
__global__ __launch_bounds__(256) void ln_split_kernel(
    const float* __restrict__ x, const float* __restrict__ w,
    const float* __restrict__ b, __nv_bfloat16* __restrict__ oh,
    __nv_bfloat16* __restrict__ ol)
{
    int row = blockIdx.x, tid = threadIdx.x;
    const float4* xr = (const float4*)(x + (size_t)row * DMODEL);
    float4 v = xr[tid];
    float mu = block_sum256(v.x + v.y + v.z + v.w) * (1.f / DMODEL);
    float4 d = {v.x - mu, v.y - mu, v.z - mu, v.w - mu};
    float var = block_sum256(d.x*d.x + d.y*d.y + d.z*d.z + d.w*d.w) * (1.f / DMODEL);
    float rs = rsqrtf(var + EPS);
    float4 wv = ((const float4*)w)[tid];
    float4 bv = ((const float4*)b)[tid];
    float4 o = {d.x*rs*wv.x + bv.x, d.y*rs*wv.y + bv.y, d.z*rs*wv.z + bv.z, d.w*rs*wv.w + bv.w};
    uint2 h, l;
    cvt_split(o, h, l);
    ((uint2*)(oh + (size_t)row * DMODEL))[tid] = h;
    ((uint2*)(ol + (size_t)row * DMODEL))[tid] = l;
}

// ---------------- GEMM via mma.sync: C[M,N] = A[M,K] @ B[N,K]^T (+ epilogue) ----------------
// Tile 128x128, K-chunk 64, cp.async double-buffered loader.
// A, B bf16 hi/lo planes. 3-term: Ah*Bh + Ah*Bl + Al*Bh (fp32 accumulate).
// EPI: 0 = none, 1 = bias+gelu(exact), 2 = +res, 3 = +bias+res
// OUTP: 0 = fp32 C, 1 = bf16 hi/lo planes (Chi/Clo)
template<int EPI>
__device__ __forceinline__ float epi_f(float v, int gn, const float* __restrict__ bias,
                                       const float* __restrict__ rrow) {
    if (EPI == 1) { v += bias[gn]; return 0.5f * v * (1.f + erff(v * 0.70710678118654752f)); }
    if (EPI == 2) return v + rrow[gn];
    if (EPI == 3) return v + bias[gn] + rrow[gn];
    return v;
}

#define ROWB   144                   // bytes per SMEM row: 64 bf16 data (128B) + 16 pad
#define PLANE  (128*ROWB)            // 18432 B
#define STAGEB (4*PLANE)             // Ah, Al, Bh, Bl = 73728 B
#define GEMM_SMEM (2*STAGEB)         // 147456 B

template<int EPI, int OUTP>
__global__ __launch_bounds__(256, 1) void gemm_mma(
    const __nv_bfloat16* __restrict__ Ahp, const __nv_bfloat16* __restrict__ Alp,
    const __nv_bfloat16* __restrict__ Bhp, const __nv_bfloat16* __restrict__ Blp,
    float* __restrict__ C, __nv_bfloat16* __restrict__ Chi, __nv_bfloat16* __restrict__ Clo,
    int M, int N, int K, const float* __restrict__ bias, const float* __restrict__ res)
{
    extern __shared__ char smem[];
    const int tid = threadIdx.x;
    const int m0 = blockIdx.y * 128, n0 = blockIdx.x * 128;
    const int warp = tid >> 5, lane = tid & 31;
    const int wm = (warp & 1) * 64;      // warp grid: 2 along M
    const int wn = (warp >> 1) * 32;     // 4 along N

    // loader: thread covers rows rq, rq+64; row-byte cols cb0, cb0+64; all 4 planes
    const int rq = tid >> 2;             // 0..63
    const int cq = tid & 3;
    const uint32_t cb0 = (uint32_t)cq * 16;   // byte col within 128B row data
    const __nv_bfloat16* Ah0 = Ahp + (size_t)(m0 + rq) * K + cq * 8;
    const __nv_bfloat16* Al0 = Alp + (size_t)(m0 + rq) * K + cq * 8;
    const __nv_bfloat16* Bh0 = Bhp + (size_t)(n0 + rq) * K + cq * 8;
    const __nv_bfloat16* Bl0 = Blp + (size_t)(n0 + rq) * K + cq * 8;
    const size_t rstep = (size_t)64 * K;
    const int sz0 = ((n0 + rq) < N) ? 16 : 0;
    const int sz1 = ((n0 + rq + 64) < N) ? 16 : 0;

    const uint32_t sbase = smem_u32(smem);
    const uint32_t d00 = (uint32_t)rq * ROWB + cb0;
    const uint32_t d01 = d00 + 64;
    const uint32_t d10 = d00 + 64 * ROWB;
    const uint32_t d11 = d10 + 64;

    float acc[4][4][4];
    #pragma unroll
    for (int mt = 0; mt < 4; mt++)
        #pragma unroll
        for (int nt = 0; nt < 4; nt++)
            #pragma unroll
            for (int r = 0; r < 4; r++) acc[mt][nt][r] = 0.f;

    // cp.async issue of one 64-wide K chunk into stage at byte offset stg
    auto issue = [&](int c, uint32_t stg) {
        const size_t kf = (size_t)c * 64;
        const uint32_t b0 = sbase + stg;
        // plane 0: Ah
        CPA16(b0 + d00, Ah0 + kf,              16);
        CPA16(b0 + d01, Ah0 + kf + 32,         16);
        CPA16(b0 + d10, Ah0 + kf + rstep,      16);
        CPA16(b0 + d11, Ah0 + kf + rstep + 32, 16);
        // plane 1: Al
        const uint32_t b1 = b0 + PLANE;
        CPA16(b1 + d00, Al0 + kf,              16);
        CPA16(b1 + d01, Al0 + kf + 32,         16);
        CPA16(b1 + d10, Al0 + kf + rstep,      16);
        CPA16(b1 + d11, Al0 + kf + rstep + 32, 16);
        // plane 2: Bh (zero-fill beyond N)
        const uint32_t b2 = b0 + 2 * PLANE;
        CPA16(b2 + d00, Bh0 + kf,              sz0);
        CPA16(b2 + d01, Bh0 + kf + 32,         sz0);
        CPA16(b2 + d10, Bh0 + kf + rstep,      sz1);
        CPA16(b2 + d11, Bh0 + kf + rstep + 32, sz1);
        // plane 3: Bl
        const uint32_t b3 = b0 + 3 * PLANE;
        CPA16(b3 + d00, Bl0 + kf,              sz0);
        CPA16(b3 + d01, Bl0 + kf + 32,         sz0);
        CPA16(b3 + d10, Bl0 + kf + rstep,      sz1);
        CPA16(b3 + d11, Bl0 + kf + rstep + 32, sz1);
    };

    issue(0, 0);
    CP_COMMIT();

    const int nch = K >> 6;   // K/64
    for (int c = 0; c < nch; c++) {
        const uint32_t stg = (uint32_t)(c & 1) * STAGEB;
        if (c + 1 < nch) {
            issue(c + 1, (uint32_t)((c + 1) & 1) * STAGEB);
            CP_COMMIT();
            asm volatile("cp.async.wait_group 1;" ::: "memory");
        } else {
            asm volatile("cp.async.wait_group 0;" ::: "memory");
        }
        __syncthreads();

        const uint32_t sb = sbase + stg;
        // compute: 4 k16 steps
        #pragma unroll
        for (int ks = 0; ks < 4; ks++) {
            const uint32_t kb = ks * 32;
            uint32_t ah[4][4], al[4][4], bh[4][2], bl[4][2];
            #pragma unroll
            for (int mt = 0; mt < 4; mt++) {
                uint32_t ar = sb + (uint32_t)(wm + mt * 16 + (lane & 15)) * ROWB
                            + kb + ((lane >> 4) << 4);
                ldsm_x4(ah[mt][0], ah[mt][1], ah[mt][2], ah[mt][3], ar);
                ldsm_x4(al[mt][0], al[mt][1], al[mt][2], al[mt][3], ar + PLANE);
            }
            const int g = lane >> 3;
            #pragma unroll
            for (int pr = 0; pr < 2; pr++) {
                uint32_t br = sb + 2 * PLANE
                            + (uint32_t)(wn + pr * 16 + ((g >> 1) << 3) + (lane & 7)) * ROWB
                            + kb + ((g & 1) << 4);
                uint32_t r0, r1, r2, r3;
                ldsm_x4(r0, r1, r2, r3, br);
                bh[2*pr][0] = r0; bh[2*pr][1] = r1; bh[2*pr+1][0] = r2; bh[2*pr+1][1] = r3;
                ldsm_x4(r0, r1, r2, r3, br + PLANE);
                bl[2*pr][0] = r0; bl[2*pr][1] = r1; bl[2*pr+1][0] = r2; bl[2*pr+1][1] = r3;
            }
            #pragma unroll
            for (int mt = 0; mt < 4; mt++)
                #pragma unroll
                for (int nt = 0; nt < 4; nt++) {
                    mma_bf16(acc[mt][nt], ah[mt], bh[nt]);
                    mma_bf16(acc[mt][nt], ah[mt], bl[nt]);
                    mma_bf16(acc[mt][nt], al[mt], bh[nt]);
                }
        }
        __syncthreads();
    }

    // epilogue: frag c0=(r, col) c1=(r, col+1) c2=(r+8, col) c3=(r+8, col+1)
    #pragma unroll
    for (int mt = 0; mt < 4; mt++) {
        const int gr = m0 + wm + mt * 16 + (lane >> 2);
        const float* R0 = (EPI >= 2) ? (res + (size_t)gr * N) : (const float*)0;
        const float* R1 = (EPI >= 2) ? (res + (size_t)(gr + 8) * N) : (const float*)0;
        #pragma unroll
        for (int nt = 0; nt < 4; nt++) {
            const int gc = n0 + wn + nt * 8 + (lane & 3) * 2;
            if (gc < N) {
                float2 v0 = { epi_f<EPI>(acc[mt][nt][0], gc,     bias, R0),
                              epi_f<EPI>(acc[mt][nt][1], gc + 1, bias, R0) };
                float2 v1 = { epi_f<EPI>(acc[mt][nt][2], gc,     bias, R1),
                              epi_f<EPI>(acc[mt][nt][3], gc + 1, bias, R1) };
                if (OUTP == 0) {
                    *(float2*)(C + (size_t)gr * N + gc) = v0;
                    *(float2*)(C + (size_t)(gr + 8) * N + gc) = v1;
                } else {
                    __nv_bfloat162 h0 = __float22bfloat162_rn(v0);
                    float2 f0 = __bfloat1622float2(h0);
                    __nv_bfloat162 l0 = __float22bfloat162_rn(make_float2(v0.x - f0.x, v0.y - f0.y));
                    __nv_bfloat162 h1 = __float22bfloat162_rn(v1);
                    float2 f1 = __bfloat1622float2(h1);
                    __nv_bfloat162 l1 = __float22bfloat162_rn(make_float2(v1.x - f1.x, v1.y - f1.y));
                    *(__nv_bfloat162*)(Chi + (size_t)gr * N + gc) = h0;
                    *(__nv_bfloat162*)(Clo + (size_t)gr * N + gc) = l0;
                    *(__nv_bfloat162*)(Chi + (size_t)(gr + 8) * N + gc) = h1;
                    *(__nv_bfloat162*)(Clo + (size_t)(gr + 8) * N + gc) = l1;
                }
            }
        }
    }
}

// ---------------- dt = softplus(zx[..., 4224:4256] + dt_bias) ----------------
__global__ __launch_bounds__(256) void dt_kernel(
    const float* __restrict__ zx, const float* __restrict__ dt_bias, float* __restrict__ dt)
{
    int idx = blockIdx.x * 256 + threadIdx.x;  // NTOK*32
    int t = idx >> 5, h = idx & 31;
    float v = zx[(size_t)t * DINPROJ + (DINNER + CONVDIM) + h] + dt_bias[h];
    dt[idx] = (v > 20.f) ? v : log1pf(__expf(v));
}

// ---------------- causal depthwise conv(4) + silu ----------------
__global__ __launch_bounds__(256) void conv_kernel(
    const float* __restrict__ zx, const float* __restrict__ cw,
    const float* __restrict__ cb, float* __restrict__ xbc)
{
    int c = blockIdx.x * 256 + threadIdx.x;
    if (c >= CONVDIM) return;
    int t = blockIdx.y;
    int b = t >> 11, tl = t & 2047;
    float acc = cb[c];
    const float* src = zx + (size_t)b * SEQ * DINPROJ + DINNER + c;
    #pragma unroll
    for (int k = 0; k < DCONV; k++) {
        int ts = tl - 3 + k;
        if (ts >= 0) acc += src[(size_t)ts * DINPROJ] * cw[c * DCONV + k];
    }
    float s = acc / (1.f + __expf(-acc));
    xbc[(size_t)t * CONVDIM + c] = s;
}

// ---------------- SSM sequential scan ----------------
__global__ __launch_bounds__(256) void scan_kernel(
    const float* __restrict__ xbc, const float* __restrict__ dtp,
    const float* __restrict__ A_log, const float* __restrict__ Dp,
    float* __restrict__ y)
{
    const int CH = 16;
    __shared__ float sx[2][CH][64], sB[2][CH][64], sC[2][CH][64];
    __shared__ float sdt[2][CH], sdA[2][CH];
    const int bh = blockIdx.x, b = bh >> 5, h = bh & 31;
    const int tid = threadIdx.x, p = tid >> 2, q = tid & 3;
    const float Ac = -expf(A_log[h]);
    const float Dv = Dp[h];
    const float* base = xbc + (size_t)b * SEQ * CONVDIM;
    const float* dtb  = dtp + (size_t)b * SEQ * NHEADS + h;
    float* yb = y + (size_t)b * SEQ * DINNER + h * HEADDIM + p;

    unsigned long long s2[8];
    #pragma unroll
    for (int j = 0; j < 8; j++) s2[j] = 0ull;

    const int rrow = tid >> 4;
    const int rc   = (tid & 15) << 2;
    const bool hasdt = tid < CH;
    const size_t xoff = (size_t)h * HEADDIM + rc;
    const size_t boff = (size_t)DINNER + rc;
    const size_t coff = (size_t)DINNER + DSTATE + rc;

    float4 rx, rB, rC; float rdt = 0.f;
    {
        const float* rowp = base + (size_t)rrow * CONVDIM;
        rx = *(const float4*)(rowp + xoff);
        rB = *(const float4*)(rowp + boff);
        rC = *(const float4*)(rowp + coff);
        if (hasdt) rdt = dtb[(size_t)tid * NHEADS];
    }
    *(float4*)&sx[0][rrow][rc] = rx;
    *(float4*)&sB[0][rrow][rc] = rB;
    *(float4*)&sC[0][rrow][rc] = rC;
    if (hasdt) { sdt[0][tid] = rdt; sdA[0][tid] = expf(rdt * Ac); }
    __syncthreads();

    const int nch = SEQ / CH;
    for (int c = 0; c < nch; c++) {
        const int cur = c & 1;
        if (c + 1 < nch) {
            const int t0 = (c + 1) * CH;
            const float* rowp = base + (size_t)(t0 + rrow) * CONVDIM;
            rx = *(const float4*)(rowp + xoff);
            rB = *(const float4*)(rowp + boff);
            rC = *(const float4*)(rowp + coff);
            if (hasdt) rdt = dtb[(size_t)(t0 + tid) * NHEADS];
        }
        for (int s = 0; s < CH; s++) {
            const float dtv = sdt[cur][s];
            const float dA  = sdA[cur][s];
            const float xv  = sx[cur][s][p];
            const float u   = dtv * xv;
            unsigned long long u2 = pk2(u, u), dA2 = pk2(dA, dA), acc2 = 0ull;
            #pragma unroll
            for (int j = 0; j < 8; j++) {
                float2 Bv = *(const float2*)&sB[cur][s][q * 16 + j * 2];
                float2 Cv = *(const float2*)&sC[cur][s][q * 16 + j * 2];
                unsigned long long t2 = mul2(u2, pk2(Bv.x, Bv.y));
                fma2(t2, s2[j], dA2);
                s2[j] = t2;
                fma2(acc2, t2, pk2(Cv.x, Cv.y));
            }
            float2 af = upk(acc2);
            float acc = af.x + af.y;
            acc += __shfl_xor_sync(0xffffffffu, acc, 1);
            acc += __shfl_xor_sync(0xffffffffu, acc, 2);
            if (q == 0) yb[(size_t)(c * CH + s) * DINNER] = acc + Dv * xv;
        }
        if (c + 1 < nch) {
            const int nx = (c + 1) & 1;
            *(float4*)&sx[nx][rrow][rc] = rx;
            *(float4*)&sB[nx][rrow][rc] = rB;
            *(float4*)&sC[nx][rrow][rc] = rC;
            if (hasdt) { sdt[nx][tid] = rdt; sdA[nx][tid] = expf(rdt * Ac); }
        }
        __syncthreads();
    }
}

// ---------------- gate (y * silu(z)) + RMSNorm, writes hi/lo planes ----------------
__global__ __launch_bounds__(256) void gate_rms_split_kernel(
    const float* __restrict__ y, const float* __restrict__ zx,
    const float* __restrict__ nw, __nv_bfloat16* __restrict__ oh,
    __nv_bfloat16* __restrict__ ol)
{
    int row = blockIdx.x, tid = threadIdx.x;
    const float4* yr = (const float4*)(y  + (size_t)row * DINNER);
    const float4* zr = (const float4*)(zx + (size_t)row * DINPROJ);
    float4 v[2]; float ss = 0.f;
    #pragma unroll
    for (int i = 0; i < 2; i++) {
        int idx = tid + i * 256;
        float4 yv = yr[idx], zv = zr[idx];
        float4 r;
        r.x = yv.x * (zv.x / (1.f + __expf(-zv.x)));
        r.y = yv.y * (zv.y / (1.f + __expf(-zv.y)));
        r.z = yv.z * (zv.z / (1.f + __expf(-zv.z)));
        r.w = yv.w * (zv.w / (1.f + __expf(-zv.w)));
        ss += r.x*r.x + r.y*r.y + r.z*r.z + r.w*r.w;
        v[i] = r;
    }
    float tot = block_sum256(ss);
    float sc = rsqrtf(tot * (1.f / DINNER) + EPS);
    const float4* nwv = (const float4*)nw;
    uint2* ohp = (uint2*)(oh + (size_t)row * DINNER);
    uint2* olp = (uint2*)(ol + (size_t)row * DINNER);
    #pragma unroll
    for (int i = 0; i < 2; i++) {
        int idx = tid + i * 256;
        float4 w = nwv[idx];
        float4 r = v[i];
        float4 o = {r.x*sc*w.x, r.y*sc*w.y, r.z*sc*w.z, r.w*sc*w.w};
        uint2 h, l;
        cvt_split(o, h, l);
        ohp[idx] = h;
        olp[idx] = l;
    }
}

// ---------------- launch ----------------
extern "C" void kernel_launch(void* const* d_in, const int* in_sizes, int n_in,
                              void* d_out, int out_size) {
    const float* x        = (const float*)d_in[0];
    const float* ln1_w    = (const float*)d_in[1];
    const float* ln1_b    = (const float*)d_in[2];
    const float* in_proj  = (const float*)d_in[3];
    const float* conv_w   = (const float*)d_in[4];
    const float* conv_b   = (const float*)d_in[5];
    const float* dt_bias  = (const float*)d_in[6];
    const float* A_log    = (const float*)d_in[7];
    const float* Dp       = (const float*)d_in[8];
    const float* norm_w   = (const float*)d_in[9];
    const float* out_proj = (const float*)d_in[10];
    const float* ln2_w    = (const float*)d_in[11];
    const float* ln2_b    = (const float*)d_in[12];
    const float* mlp_w1   = (const float*)d_in[13];
    const float* mlp_b1   = (const float*)d_in[14];
    const float* mlp_w2   = (const float*)d_in[15];
    const float* mlp_b2   = (const float*)d_in[16];
    float* out = (float*)d_out;

    float *zx, *xbc, *dt, *y, *x2;
    cudaGetSymbolAddress((void**)&zx,  g_zx);
    cudaGetSymbolAddress((void**)&xbc, g_xbc);
    cudaGetSymbolAddress((void**)&dt,  g_dt);
    cudaGetSymbolAddress((void**)&y,   g_y);
    cudaGetSymbolAddress((void**)&x2,  g_x2);
    __nv_bfloat16 *h1h,*h1l,*ynh,*ynl,*h2h,*h2l,*mdh,*mdl;
    __nv_bfloat16 *wih,*wil,*woh,*wol,*w1h,*w1l,*w2h,*w2l;
    cudaGetSymbolAddress((void**)&h1h, g_h1h); cudaGetSymbolAddress((void**)&h1l, g_h1l);
    cudaGetSymbolAddress((void**)&ynh, g_ynh); cudaGetSymbolAddress((void**)&ynl, g_ynl);
    cudaGetSymbolAddress((void**)&h2h, g_h2h); cudaGetSymbolAddress((void**)&h2l, g_h2l);
    cudaGetSymbolAddress((void**)&mdh, g_mdh); cudaGetSymbolAddress((void**)&mdl, g_mdl);
    cudaGetSymbolAddress((void**)&wih, g_wih); cudaGetSymbolAddress((void**)&wil, g_wil);
    cudaGetSymbolAddress((void**)&woh, g_woh); cudaGetSymbolAddress((void**)&wol, g_wol);
    cudaGetSymbolAddress((void**)&w1h, g_w1h); cudaGetSymbolAddress((void**)&w1l, g_w1l);
    cudaGetSymbolAddress((void**)&w2h, g_w2h); cudaGetSymbolAddress((void**)&w2l, g_w2l);

    cudaFuncSetAttribute(gemm_mma<0,0>, cudaFuncAttributeMaxDynamicSharedMemorySize, GEMM_SMEM);
    cudaFuncSetAttribute(gemm_mma<1,1>, cudaFuncAttributeMaxDynamicSharedMemorySize, GEMM_SMEM);
    cudaFuncSetAttribute(gemm_mma<2,0>, cudaFuncAttributeMaxDynamicSharedMemorySize, GEMM_SMEM);
    cudaFuncSetAttribute(gemm_mma<3,0>, cudaFuncAttributeMaxDynamicSharedMemorySize, GEMM_SMEM);

    // 0. weight splits (once per launch)
    split_kernel<<<(DINPROJ*DMODEL/4 + 255)/256, 256>>>(in_proj,  wih, wil, DINPROJ*DMODEL/4);
    split_kernel<<<(DMODEL*DINNER/4 + 255)/256, 256>>>(out_proj, woh, wol, DMODEL*DINNER/4);
    split_kernel<<<(DMLP*DMODEL/4 + 255)/256, 256>>>(mlp_w1,   w1h, w1l, DMLP*DMODEL/4);
    split_kernel<<<(DMODEL*DMLP/4 + 255)/256, 256>>>(mlp_w2,   w2h, w2l, DMODEL*DMLP/4);

    // 1. LN1 -> h1 planes
    ln_split_kernel<<<NTOK, 256>>>(x, ln1_w, ln1_b, h1h, h1l);
    // 2. in_proj -> zx (fp32)
    gemm_mma<0,0><<<dim3((DINPROJ + 127) / 128, NTOK / 128), 256, GEMM_SMEM>>>(
        h1h, h1l, wih, wil, zx, nullptr, nullptr, NTOK, DINPROJ, DMODEL, nullptr, nullptr);
    // 3. dt
    dt_kernel<<<(NTOK * NHEADS) / 256, 256>>>(zx, dt_bias, dt);
    // 4. conv + silu
    conv_kernel<<<dim3((CONVDIM + 255) / 256, NTOK), 256>>>(zx, conv_w, conv_b, xbc);
    // 5. scan
    scan_kernel<<<BATCH * NHEADS, 256>>>(xbc, dt, A_log, Dp, y);
    // 6. gate + rmsnorm -> yn planes
    gate_rms_split_kernel<<<NTOK, 256>>>(y, zx, norm_w, ynh, ynl);
    // 7. out_proj + residual(x) -> x2 (fp32)
    gemm_mma<2,0><<<dim3(DMODEL / 128, NTOK / 128), 256, GEMM_SMEM>>>(
        ynh, ynl, woh, wol, x2, nullptr, nullptr, NTOK, DMODEL, DINNER, nullptr, x);
    // 8. LN2 -> h2 planes
    ln_split_kernel<<<NTOK, 256>>>(x2, ln2_w, ln2_b, h2h, h2l);
    // 9. mlp1 + bias + gelu -> mid planes
    gemm_mma<1,1><<<dim3(DMLP / 128, NTOK / 128), 256, GEMM_SMEM>>>(
        h2h, h2l, w1h, w1l, nullptr, mdh, mdl, NTOK, DMLP, DMODEL, mlp_b1, nullptr);
    // 10. mlp2 + bias + residual(x2) -> out (fp32)
    gemm_mma<3,0><<<dim3(DMODEL / 128, NTOK / 128), 256, GEMM_SMEM>>>(
        mdh, mdl, w2h, w2l, out, nullptr, nullptr, NTOK, DMODEL, DMLP, mlp_b2, x2);
}

// round 16
// speedup vs baseline: 1.5521x; 1.2224x over previous
#include <cuda_runtime.h>
#include <cuda_bf16.h>
#include <math.h>
#include <stdint.h>

// ---------------- Problem constants ----------------
#define BATCH   2
#define SEQ     2048
#define NTOK    (BATCH*SEQ)          // 4096
#define DMODEL  1024
#define DINNER  2048
#define NHEADS  32
#define HEADDIM 64
#define DSTATE  64
#define DCONV   4
#define CONVDIM 2176                 // DINNER + 2*DSTATE
#define DINPROJ 4256                 // 2*DINNER + 2*DSTATE + NHEADS
#define DMLP    4096
#define EPS     1e-5f

// ---------------- Scratch (device globals; no allocation allowed) ----------------
__device__ float g_zx [NTOK*DINPROJ];
__device__ float g_xbc[NTOK*CONVDIM];
__device__ float g_dt [NTOK*NHEADS];
__device__ float g_y  [NTOK*DINNER];
__device__ float g_x2 [NTOK*DMODEL];
// activation bf16 hi/lo planes (GEMM A operands)
__device__ __nv_bfloat16 g_h1h[NTOK*DMODEL],  g_h1l[NTOK*DMODEL];
__device__ __nv_bfloat16 g_ynh[NTOK*DINNER],  g_ynl[NTOK*DINNER];
__device__ __nv_bfloat16 g_h2h[NTOK*DMODEL],  g_h2l[NTOK*DMODEL];
__device__ __nv_bfloat16 g_mdh[NTOK*DMLP],    g_mdl[NTOK*DMLP];
// weight bf16 hi/lo planes (GEMM B operands)
__device__ __nv_bfloat16 g_wih[DINPROJ*DMODEL], g_wil[DINPROJ*DMODEL];
__device__ __nv_bfloat16 g_woh[DMODEL*DINNER],  g_wol[DMODEL*DINNER];
__device__ __nv_bfloat16 g_w1h[DMLP*DMODEL],    g_w1l[DMLP*DMODEL];
__device__ __nv_bfloat16 g_w2h[DMODEL*DMLP],    g_w2l[DMODEL*DMLP];

// ---------------- f32x2 packed helpers (scan) ----------------
__device__ __forceinline__ unsigned long long pk2(float x, float y) {
    unsigned long long r;
    asm("mov.b64 %0, {%1, %2};" : "=l"(r) : "f"(x), "f"(y));
    return r;
}
__device__ __forceinline__ float2 upk(unsigned long long v) {
    float2 f;
    asm("mov.b64 {%0, %1}, %2;" : "=f"(f.x), "=f"(f.y) : "l"(v));
    return f;
}
__device__ __forceinline__ void fma2(unsigned long long &d, unsigned long long a, unsigned long long b) {
    asm("fma.rn.f32x2 %0, %1, %2, %0;" : "+l"(d) : "l"(a), "l"(b));
}
__device__ __forceinline__ unsigned long long mul2(unsigned long long a, unsigned long long b) {
    unsigned long long r;
    asm("mul.rn.f32x2 %0, %1, %2;" : "=l"(r) : "l"(a), "l"(b));
    return r;
}

// ---------------- mma.sync helpers (portable sm_80+ PTX) ----------------
__device__ __forceinline__ uint32_t smem_u32(const void* p) {
    uint32_t a;
    asm("{ .reg .u64 t; cvta.to.shared.u64 t, %1; cvt.u32.u64 %0, t; }" : "=r"(a) : "l"(p));
    return a;
}
__device__ __forceinline__ void ldsm_x4(uint32_t &r0, uint32_t &r1, uint32_t &r2, uint32_t &r3,
                                        uint32_t addr) {
    asm volatile("ldmatrix.sync.aligned.m8n8.x4.shared.b16 {%0,%1,%2,%3}, [%4];"
                 : "=r"(r0), "=r"(r1), "=r"(r2), "=r"(r3) : "r"(addr));
}
__device__ __forceinline__ void mma_bf16(float* c, const uint32_t* a, const uint32_t* b) {
    asm volatile(
        "mma.sync.aligned.m16n8k16.row.col.f32.bf16.bf16.f32 "
        "{%0,%1,%2,%3}, {%4,%5,%6,%7}, {%8,%9}, {%0,%1,%2,%3};"
        : "+f"(c[0]), "+f"(c[1]), "+f"(c[2]), "+f"(c[3])
        : "r"(a[0]), "r"(a[1]), "r"(a[2]), "r"(a[3]), "r"(b[0]), "r"(b[1]));
}

// ---------------- bf16 hi/lo split ----------------
__device__ __forceinline__ void cvt_split(float4 v, uint2 &hi, uint2 &lo) {
    __nv_bfloat162 h0 = __float22bfloat162_rn(make_float2(v.x, v.y));
    __nv_bfloat162 h1 = __float22bfloat162_rn(make_float2(v.z, v.w));
    float2 f0 = __bfloat1622float2(h0);
    float2 f1 = __bfloat1622float2(h1);
    __nv_bfloat162 l0 = __float22bfloat162_rn(make_float2(v.x - f0.x, v.y - f0.y));
    __nv_bfloat162 l1 = __float22bfloat162_rn(make_float2(v.z - f1.x, v.w - f1.y));
    hi.x = *(uint32_t*)&h0; hi.y = *(uint32_t*)&h1;
    lo.x = *(uint32_t*)&l0; lo.y = *(uint32_t*)&l1;
}

// ---------------- weight split: fp32 -> hi/lo bf16 planes ----------------
__global__ __launch_bounds__(256) void split_kernel(
    const float* __restrict__ src, __nv_bfloat16* __restrict__ hi,
    __nv_bfloat16* __restrict__ lo, int n4)
{
    int i = blockIdx.x * 256 + threadIdx.x;
    if (i >= n4) return;
    float4 v = ((const float4*)src)[i];
    uint2 h, l;
    cvt_split(v, h, l);
    ((uint2*)hi)[i] = h;
    ((uint2*)lo)[i] = l;
}

// ---------------- block reduction (256 threads) ----------------
__device__ __forceinline__ float block_sum256(float v) {
    __shared__ float sb[8];
    #pragma unroll
    for (int o = 16; o; o >>= 1) v += __shfl_xor_sync(0xffffffffu, v, o);
    int w = threadIdx.x >> 5;
    if ((threadIdx.x & 31) == 0) sb[w] = v;
    __syncthreads();
    if (threadIdx.x == 0) {
        float t = 0.f;
        #pragma unroll
        for (int i = 0; i < 8; i++) t += sb[i];
        sb[0] = t;
    }
    __syncthreads();
    float r = sb[0];
    __syncthreads();
    return r;
}

// ---------------- LayerNorm: rows of 1024, writes hi/lo bf16 planes ----------------
__global__ __launch_bounds__(256) void ln_split_kernel(
    const float* __restrict__ x, const float* __restrict__ w,
    const float* __restrict__ b, __nv_bfloat16* __restrict__ oh,
    __nv_bfloat16* __restrict__ ol)
{
    int row = blockIdx.x, tid = threadIdx.x;
    const float4* xr = (const float4*)(x + (size_t)row * DMODEL);
    float4 v = xr[tid];
    float mu = block_sum256(v.x + v.y + v.z + v.w) * (1.f / DMODEL);
    float4 d = {v.x - mu, v.y - mu, v.z - mu, v.w - mu};
    float var = block_sum256(d.x*d.x + d.y*d.y + d.z*d.z + d.w*d.w) * (1.f / DMODEL);
    float rs = rsqrtf(var + EPS);
    float4 wv = ((const float4*)w)[tid];
    float4 bv = ((const float4*)b)[tid];
    float4 o = {d.x*rs*wv.x + bv.x, d.y*rs*wv.y + bv.y, d.z*rs*wv.z + bv.z, d.w*rs*wv.w + bv.w};
    uint2 h, l;
    cvt_split(o, h, l);
    ((uint2*)(oh + (size_t)row * DMODEL))[tid] = h;
    ((uint2*)(ol + (size_t)row * DMODEL))[tid] = l;
}

// ---------------- GEMM via mma.sync: C[M,N] = A[M,K] @ B[N,K]^T (+ epilogue) ----------------
// R11 champion config: tile 128x128, K-chunk 32, LDG->reg->STS double buffer.
// A, B bf16 hi/lo planes. 3-term: Ah*Bh + Ah*Bl + Al*Bh (fp32 accumulate).
// EPI: 0 = none, 1 = bias+gelu(exact), 2 = +res, 3 = +bias+res
// OUTP: 0 = fp32 C, 1 = bf16 hi/lo planes (Chi/Clo)
template<int EPI>
__device__ __forceinline__ float epi_f(float v, int gn, const float* __restrict__ bias,
                                       const float* __restrict__ rrow) {
    if (EPI == 1) { v += bias[gn]; return 0.5f * v * (1.f + erff(v * 0.70710678118654752f)); }
    if (EPI == 2) return v + rrow[gn];
    if (EPI == 3) return v + bias[gn] + rrow[gn];
    return v;
}

#define ROWB   80                    // bytes per SMEM row: 32 bf16 data + 8 pad
#define PLANE  (128*ROWB)            // 10240 B
#define STAGEB (4*PLANE)             // Ah, Al, Bh, Bl = 40960 B
#define GEMM_SMEM (2*STAGEB)         // 81920 B

template<int EPI, int OUTP>
__global__ __launch_bounds__(256, 1) void gemm_mma(
    const __nv_bfloat16* __restrict__ Ahp, const __nv_bfloat16* __restrict__ Alp,
    const __nv_bfloat16* __restrict__ Bhp, const __nv_bfloat16* __restrict__ Blp,
    float* __restrict__ C, __nv_bfloat16* __restrict__ Chi, __nv_bfloat16* __restrict__ Clo,
    int M, int N, int K, const float* __restrict__ bias, const float* __restrict__ res)
{
    extern __shared__ char smem[];
    const int tid = threadIdx.x;
    const int m0 = blockIdx.y * 128, n0 = blockIdx.x * 128;
    const int warp = tid >> 5, lane = tid & 31;
    const int wm = (warp & 1) * 64;      // warp grid: 2 along M
    const int wn = (warp >> 1) * 32;     // 4 along N

    // loader: thread covers 8 bf16 (16B) at k-offset (tid&3)*8 of rows rq and rq+64
    const int rq = tid >> 2;             // 0..63
    const int kc = (tid & 3) * 8;        // bf16 k offset within 32-wide chunk
    const __nv_bfloat16* Ah0 = Ahp + (size_t)(m0 + rq) * K + kc;
    const __nv_bfloat16* Al0 = Alp + (size_t)(m0 + rq) * K + kc;
    const __nv_bfloat16* Bh0 = Bhp + (size_t)(n0 + rq) * K + kc;
    const __nv_bfloat16* Bl0 = Blp + (size_t)(n0 + rq) * K + kc;
    const size_t rstep = (size_t)64 * K;
    const bool bok0 = (n0 + rq) < N;
    const bool bok1 = (n0 + rq + 64) < N;
    const uint32_t wb = (uint32_t)rq * ROWB + (tid & 3) * 16;

    const uint32_t sbase = smem_u32(smem);

    float acc[4][4][4];
    #pragma unroll
    for (int mt = 0; mt < 4; mt++)
        #pragma unroll
        for (int nt = 0; nt < 4; nt++)
            #pragma unroll
            for (int r = 0; r < 4; r++) acc[mt][nt][r] = 0.f;

    const uint4 z4 = {0u, 0u, 0u, 0u};
    uint4 vah0, vah1, val0, val1, vbh0, vbh1;
    uint4 vbl0, vbl1;

    // prologue: chunk 0 -> stage 0
    vah0 = *(const uint4*)(Ah0);
    vah1 = *(const uint4*)(Ah0 + rstep);
    val0 = *(const uint4*)(Al0);
    val1 = *(const uint4*)(Al0 + rstep);
    vbh0 = bok0 ? *(const uint4*)(Bh0) : z4;
    vbh1 = bok1 ? *(const uint4*)(Bh0 + rstep) : z4;
    vbl0 = bok0 ? *(const uint4*)(Bl0) : z4;
    vbl1 = bok1 ? *(const uint4*)(Bl0 + rstep) : z4;
    {
        char* st = smem;
        *(uint4*)(st + 0 * PLANE + wb)            = vah0;
        *(uint4*)(st + 0 * PLANE + wb + 64*ROWB)  = vah1;
        *(uint4*)(st + 1 * PLANE + wb)            = val0;
        *(uint4*)(st + 1 * PLANE + wb + 64*ROWB)  = val1;
        *(uint4*)(st + 2 * PLANE + wb)            = vbh0;
        *(uint4*)(st + 2 * PLANE + wb + 64*ROWB)  = vbh1;
        *(uint4*)(st + 3 * PLANE + wb)            = vbl0;
        *(uint4*)(st + 3 * PLANE + wb + 64*ROWB)  = vbl1;
    }
    __syncthreads();

    const int nch = K >> 5;   // K/32
    for (int c = 0; c < nch; c++) {
        const int cur = c & 1;
        const uint32_t sb = sbase + cur * STAGEB;

        if (c + 1 < nch) {
            const size_t kf = (size_t)(c + 1) * 32;
            vah0 = *(const uint4*)(Ah0 + kf);
            vah1 = *(const uint4*)(Ah0 + kf + rstep);
            val0 = *(const uint4*)(Al0 + kf);
            val1 = *(const uint4*)(Al0 + kf + rstep);
            vbh0 = bok0 ? *(const uint4*)(Bh0 + kf) : z4;
            vbh1 = bok1 ? *(const uint4*)(Bh0 + kf + rstep) : z4;
            vbl0 = bok0 ? *(const uint4*)(Bl0 + kf) : z4;
            vbl1 = bok1 ? *(const uint4*)(Bl0 + kf + rstep) : z4;
        }

        // compute: 2 k16 steps
        #pragma unroll
        for (int ks = 0; ks < 2; ks++) {
            const uint32_t kb = ks * 32;
            uint32_t ah[4][4], al[4][4], bh[4][2], bl[4][2];
            #pragma unroll
            for (int mt = 0; mt < 4; mt++) {
                uint32_t ar = sb + (uint32_t)(wm + mt * 16 + (lane & 15)) * ROWB
                            + kb + ((lane >> 4) << 4);
                ldsm_x4(ah[mt][0], ah[mt][1], ah[mt][2], ah[mt][3], ar);
                ldsm_x4(al[mt][0], al[mt][1], al[mt][2], al[mt][3], ar + PLANE);
            }
            const int g = lane >> 3;
            #pragma unroll
            for (int pr = 0; pr < 2; pr++) {
                uint32_t br = sb + 2 * PLANE
                            + (uint32_t)(wn + pr * 16 + ((g >> 1) << 3) + (lane & 7)) * ROWB
                            + kb + ((g & 1) << 4);
                uint32_t r0, r1, r2, r3;
                ldsm_x4(r0, r1, r2, r3, br);
                bh[2*pr][0] = r0; bh[2*pr][1] = r1; bh[2*pr+1][0] = r2; bh[2*pr+1][1] = r3;
                ldsm_x4(r0, r1, r2, r3, br + PLANE);
                bl[2*pr][0] = r0; bl[2*pr][1] = r1; bl[2*pr+1][0] = r2; bl[2*pr+1][1] = r3;
            }
            #pragma unroll
            for (int mt = 0; mt < 4; mt++)
                #pragma unroll
                for (int nt = 0; nt < 4; nt++) {
                    mma_bf16(acc[mt][nt], ah[mt], bh[nt]);
                    mma_bf16(acc[mt][nt], ah[mt], bl[nt]);
                    mma_bf16(acc[mt][nt], al[mt], bh[nt]);
                }
        }

        if (c + 1 < nch) {
            char* st = smem + (cur ^ 1) * STAGEB;
            *(uint4*)(st + 0 * PLANE + wb)            = vah0;
            *(uint4*)(st + 0 * PLANE + wb + 64*ROWB)  = vah1;
            *(uint4*)(st + 1 * PLANE + wb)            = val0;
            *(uint4*)(st + 1 * PLANE + wb + 64*ROWB)  = val1;
            *(uint4*)(st + 2 * PLANE + wb)            = vbh0;
            *(uint4*)(st + 2 * PLANE + wb + 64*ROWB)  = vbh1;
            *(uint4*)(st + 3 * PLANE + wb)            = vbl0;
            *(uint4*)(st + 3 * PLANE + wb + 64*ROWB)  = vbl1;
        }
        __syncthreads();
    }

    // epilogue: frag c0=(r, col) c1=(r, col+1) c2=(r+8, col) c3=(r+8, col+1)
    #pragma unroll
    for (int mt = 0; mt < 4; mt++) {
        const int gr = m0 + wm + mt * 16 + (lane >> 2);
        const float* R0 = (EPI >= 2) ? (res + (size_t)gr * N) : (const float*)0;
        const float* R1 = (EPI >= 2) ? (res + (size_t)(gr + 8) * N) : (const float*)0;
        #pragma unroll
        for (int nt = 0; nt < 4; nt++) {
            const int gc = n0 + wn + nt * 8 + (lane & 3) * 2;
            if (gc < N) {
                float2 v0 = { epi_f<EPI>(acc[mt][nt][0], gc,     bias, R0),
                              epi_f<EPI>(acc[mt][nt][1], gc + 1, bias, R0) };
                float2 v1 = { epi_f<EPI>(acc[mt][nt][2], gc,     bias, R1),
                              epi_f<EPI>(acc[mt][nt][3], gc + 1, bias, R1) };
                if (OUTP == 0) {
                    *(float2*)(C + (size_t)gr * N + gc) = v0;
                    *(float2*)(C + (size_t)(gr + 8) * N + gc) = v1;
                } else {
                    __nv_bfloat162 h0 = __float22bfloat162_rn(v0);
                    float2 f0 = __bfloat1622float2(h0);
                    __nv_bfloat162 l0 = __float22bfloat162_rn(make_float2(v0.x - f0.x, v0.y - f0.y));
                    __nv_bfloat162 h1 = __float22bfloat162_rn(v1);
                    float2 f1 = __bfloat1622float2(h1);
                    __nv_bfloat162 l1 = __float22bfloat162_rn(make_float2(v1.x - f1.x, v1.y - f1.y));
                    *(__nv_bfloat162*)(Chi + (size_t)gr * N + gc) = h0;
                    *(__nv_bfloat162*)(Clo + (size_t)gr * N + gc) = l0;
                    *(__nv_bfloat162*)(Chi + (size_t)(gr + 8) * N + gc) = h1;
                    *(__nv_bfloat162*)(Clo + (size_t)(gr + 8) * N + gc) = l1;
                }
            }
        }
    }
}

// ---------------- dt = softplus(zx[..., 4224:4256] + dt_bias) ----------------
__global__ __launch_bounds__(256) void dt_kernel(
    const float* __restrict__ zx, const float* __restrict__ dt_bias, float* __restrict__ dt)
{
    int idx = blockIdx.x * 256 + threadIdx.x;  // NTOK*32
    int t = idx >> 5, h = idx & 31;
    float v = zx[(size_t)t * DINPROJ + (DINNER + CONVDIM) + h] + dt_bias[h];
    dt[idx] = (v > 20.f) ? v : log1pf(__expf(v));
}

// ---------------- causal depthwise conv(4) + silu ----------------
__global__ __launch_bounds__(256) void conv_kernel(
    const float* __restrict__ zx, const float* __restrict__ cw,
    const float* __restrict__ cb, float* __restrict__ xbc)
{
    int c = blockIdx.x * 256 + threadIdx.x;
    if (c >= CONVDIM) return;
    int t = blockIdx.y;
    int b = t >> 11, tl = t & 2047;
    float acc = cb[c];
    const float* src = zx + (size_t)b * SEQ * DINPROJ + DINNER + c;
    #pragma unroll
    for (int k = 0; k < DCONV; k++) {
        int ts = tl - 3 + k;
        if (ts >= 0) acc += src[(size_t)ts * DINPROJ] * cw[c * DCONV + k];
    }
    float s = acc / (1.f + __expf(-acc));
    xbc[(size_t)t * CONVDIM + c] = s;
}

// ---------------- SSM sequential scan: 2 blocks per (b,h), split along HEADDIM ----------------
// block = (bh, half): covers p in [half*32, half*32+32). 128 threads:
// p = tid>>2 (local row 0..31), q = tid&3 owns 16 n (8 f32x2). Same per-thread
// arithmetic as the 256-thread version -> bit-identical outputs.
__global__ __launch_bounds__(128) void scan_kernel(
    const float* __restrict__ xbc, const float* __restrict__ dtp,
    const float* __restrict__ A_log, const float* __restrict__ Dp,
    float* __restrict__ y)
{
    const int CH = 16;
    __shared__ float sx[2][CH][32], sB[2][CH][64], sC[2][CH][64];
    __shared__ float sdt[2][CH], sdA[2][CH];
    const int blk = blockIdx.x;              // 0..127
    const int half = blk & 1, bh = blk >> 1;
    const int b = bh >> 5, h = bh & 31;
    const int tid = threadIdx.x;             // 0..127
    const int p = tid >> 2, q = tid & 3;
    const float Ac = -expf(A_log[h]);
    const float Dv = Dp[h];
    const float* base = xbc + (size_t)b * SEQ * CONVDIM;
    const float* dtb  = dtp + (size_t)b * SEQ * NHEADS + h;
    float* yb = y + (size_t)b * SEQ * DINNER + h * HEADDIM + half * 32 + p;

    unsigned long long s2[8];
    #pragma unroll
    for (int j = 0; j < 8; j++) s2[j] = 0ull;

    // loader plan: 640 float4 per chunk (16 rows x 40: 8 x-half + 16 B + 16 C),
    // 5 per thread at flat idx = tid + k*128. Precompute row/off/dst once.
    int lrow[5]; size_t loff[5]; int lsel[5]; int lcol[5];
    #pragma unroll
    for (int k = 0; k < 5; k++) {
        int idx = tid + k * 128;
        int row = idx / 40, w = idx % 40;
        lrow[k] = row;
        if (w < 8)       { lsel[k] = 0; lcol[k] = w * 4;        loff[k] = (size_t)h * HEADDIM + half * 32 + w * 4; }
        else if (w < 24) { lsel[k] = 1; lcol[k] = (w - 8) * 4;  loff[k] = (size_t)DINNER + (w - 8) * 4; }
        else             { lsel[k] = 2; lcol[k] = (w - 24) * 4; loff[k] = (size_t)DINNER + DSTATE + (w - 24) * 4; }
    }
    const bool hasdt = tid < CH;

    float4 rv[5]; float rdt = 0.f;
    #pragma unroll
    for (int k = 0; k < 5; k++)
        rv[k] = *(const float4*)(base + (size_t)lrow[k] * CONVDIM + loff[k]);
    if (hasdt) rdt = dtb[(size_t)tid * NHEADS];

    #pragma unroll
    for (int k = 0; k < 5; k++) {
        float* d = (lsel[k] == 0) ? &sx[0][lrow[k]][lcol[k]]
                 : (lsel[k] == 1) ? &sB[0][lrow[k]][lcol[k]]
                                  : &sC[0][lrow[k]][lcol[k]];
        *(float4*)d = rv[k];
    }
    if (hasdt) { sdt[0][tid] = rdt; sdA[0][tid] = expf(rdt * Ac); }
    __syncthreads();

    const int nch = SEQ / CH;  // 128
    for (int c = 0; c < nch; c++) {
        const int cur = c & 1;
        if (c + 1 < nch) {
            const int t0 = (c + 1) * CH;
            #pragma unroll
            for (int k = 0; k < 5; k++)
                rv[k] = *(const float4*)(base + (size_t)(t0 + lrow[k]) * CONVDIM + loff[k]);
            if (hasdt) rdt = dtb[(size_t)(t0 + tid) * NHEADS];
        }
        for (int s = 0; s < CH; s++) {
            const float dtv = sdt[cur][s];
            const float dA  = sdA[cur][s];
            const float xv  = sx[cur][s][p];
            const float u   = dtv * xv;
            unsigned long long u2 = pk2(u, u), dA2 = pk2(dA, dA), acc2 = 0ull;
            #pragma unroll
            for (int j = 0; j < 8; j++) {
                float2 Bv = *(const float2*)&sB[cur][s][q * 16 + j * 2];
                float2 Cv = *(const float2*)&sC[cur][s][q * 16 + j * 2];
                unsigned long long t2 = mul2(u2, pk2(Bv.x, Bv.y));
                fma2(t2, s2[j], dA2);
                s2[j] = t2;
                fma2(acc2, t2, pk2(Cv.x, Cv.y));
            }
            float2 af = upk(acc2);
            float acc = af.x + af.y;
            acc += __shfl_xor_sync(0xffffffffu, acc, 1);
            acc += __shfl_xor_sync(0xffffffffu, acc, 2);
            if (q == 0) yb[(size_t)(c * CH + s) * DINNER] = acc + Dv * xv;
        }
        if (c + 1 < nch) {
            const int nx = (c + 1) & 1;
            #pragma unroll
            for (int k = 0; k < 5; k++) {
                float* d = (lsel[k] == 0) ? &sx[nx][lrow[k]][lcol[k]]
                         : (lsel[k] == 1) ? &sB[nx][lrow[k]][lcol[k]]
                                          : &sC[nx][lrow[k]][lcol[k]];
                *(float4*)d = rv[k];
            }
            if (hasdt) { sdt[nx][tid] = rdt; sdA[nx][tid] = expf(rdt * Ac); }
        }
        __syncthreads();
    }
}

// ---------------- gate (y * silu(z)) + RMSNorm, writes hi/lo planes ----------------
__global__ __launch_bounds__(256) void gate_rms_split_kernel(
    const float* __restrict__ y, const float* __restrict__ zx,
    const float* __restrict__ nw, __nv_bfloat16* __restrict__ oh,
    __nv_bfloat16* __restrict__ ol)
{
    int row = blockIdx.x, tid = threadIdx.x;
    const float4* yr = (const float4*)(y  + (size_t)row * DINNER);
    const float4* zr = (const float4*)(zx + (size_t)row * DINPROJ);
    float4 v[2]; float ss = 0.f;
    #pragma unroll
    for (int i = 0; i < 2; i++) {
        int idx = tid + i * 256;
        float4 yv = yr[idx], zv = zr[idx];
        float4 r;
        r.x = yv.x * (zv.x / (1.f + __expf(-zv.x)));
        r.y = yv.y * (zv.y / (1.f + __expf(-zv.y)));
        r.z = yv.z * (zv.z / (1.f + __expf(-zv.z)));
        r.w = yv.w * (zv.w / (1.f + __expf(-zv.w)));
        ss += r.x*r.x + r.y*r.y + r.z*r.z + r.w*r.w;
        v[i] = r;
    }
    float tot = block_sum256(ss);
    float sc = rsqrtf(tot * (1.f / DINNER) + EPS);
    const float4* nwv = (const float4*)nw;
    uint2* ohp = (uint2*)(oh + (size_t)row * DINNER);
    uint2* olp = (uint2*)(ol + (size_t)row * DINNER);
    #pragma unroll
    for (int i = 0; i < 2; i++) {
        int idx = tid + i * 256;
        float4 w = nwv[idx];
        float4 r = v[i];
        float4 o = {r.x*sc*w.x, r.y*sc*w.y, r.z*sc*w.z, r.w*sc*w.w};
        uint2 h, l;
        cvt_split(o, h, l);
        ohp[idx] = h;
        olp[idx] = l;
    }
}

// ---------------- launch ----------------
extern "C" void kernel_launch(void* const* d_in, const int* in_sizes, int n_in,
                              void* d_out, int out_size) {
    const float* x        = (const float*)d_in[0];
    const float* ln1_w    = (const float*)d_in[1];
    const float* ln1_b    = (const float*)d_in[2];
    const float* in_proj  = (const float*)d_in[3];
    const float* conv_w   = (const float*)d_in[4];
    const float* conv_b   = (const float*)d_in[5];
    const float* dt_bias  = (const float*)d_in[6];
    const float* A_log    = (const float*)d_in[7];
    const float* Dp       = (const float*)d_in[8];
    const float* norm_w   = (const float*)d_in[9];
    const float* out_proj = (const float*)d_in[10];
    const float* ln2_w    = (const float*)d_in[11];
    const float* ln2_b    = (const float*)d_in[12];
    const float* mlp_w1   = (const float*)d_in[13];
    const float* mlp_b1   = (const float*)d_in[14];
    const float* mlp_w2   = (const float*)d_in[15];
    const float* mlp_b2   = (const float*)d_in[16];
    float* out = (float*)d_out;

    float *zx, *xbc, *dt, *y, *x2;
    cudaGetSymbolAddress((void**)&zx,  g_zx);
    cudaGetSymbolAddress((void**)&xbc, g_xbc);
    cudaGetSymbolAddress((void**)&dt,  g_dt);
    cudaGetSymbolAddress((void**)&y,   g_y);
    cudaGetSymbolAddress((void**)&x2,  g_x2);
    __nv_bfloat16 *h1h,*h1l,*ynh,*ynl,*h2h,*h2l,*mdh,*mdl;
    __nv_bfloat16 *wih,*wil,*woh,*wol,*w1h,*w1l,*w2h,*w2l;
    cudaGetSymbolAddress((void**)&h1h, g_h1h); cudaGetSymbolAddress((void**)&h1l, g_h1l);
    cudaGetSymbolAddress((void**)&ynh, g_ynh); cudaGetSymbolAddress((void**)&ynl, g_ynl);
    cudaGetSymbolAddress((void**)&h2h, g_h2h); cudaGetSymbolAddress((void**)&h2l, g_h2l);
    cudaGetSymbolAddress((void**)&mdh, g_mdh); cudaGetSymbolAddress((void**)&mdl, g_mdl);
    cudaGetSymbolAddress((void**)&wih, g_wih); cudaGetSymbolAddress((void**)&wil, g_wil);
    cudaGetSymbolAddress((void**)&woh, g_woh); cudaGetSymbolAddress((void**)&wol, g_wol);
    cudaGetSymbolAddress((void**)&w1h, g_w1h); cudaGetSymbolAddress((void**)&w1l, g_w1l);
    cudaGetSymbolAddress((void**)&w2h, g_w2h); cudaGetSymbolAddress((void**)&w2l, g_w2l);

    cudaFuncSetAttribute(gemm_mma<0,0>, cudaFuncAttributeMaxDynamicSharedMemorySize, GEMM_SMEM);
    cudaFuncSetAttribute(gemm_mma<1,1>, cudaFuncAttributeMaxDynamicSharedMemorySize, GEMM_SMEM);
    cudaFuncSetAttribute(gemm_mma<2,0>, cudaFuncAttributeMaxDynamicSharedMemorySize, GEMM_SMEM);
    cudaFuncSetAttribute(gemm_mma<3,0>, cudaFuncAttributeMaxDynamicSharedMemorySize, GEMM_SMEM);

    // 0. weight splits (once per launch)
    split_kernel<<<(DINPROJ*DMODEL/4 + 255)/256, 256>>>(in_proj,  wih, wil, DINPROJ*DMODEL/4);
    split_kernel<<<(DMODEL*DINNER/4 + 255)/256, 256>>>(out_proj, woh, wol, DMODEL*DINNER/4);
    split_kernel<<<(DMLP*DMODEL/4 + 255)/256, 256>>>(mlp_w1,   w1h, w1l, DMLP*DMODEL/4);
    split_kernel<<<(DMODEL*DMLP/4 + 255)/256, 256>>>(mlp_w2,   w2h, w2l, DMODEL*DMLP/4);

    // 1. LN1 -> h1 planes
    ln_split_kernel<<<NTOK, 256>>>(x, ln1_w, ln1_b, h1h, h1l);
    // 2. in_proj -> zx (fp32)
    gemm_mma<0,0><<<dim3((DINPROJ + 127) / 128, NTOK / 128), 256, GEMM_SMEM>>>(
        h1h, h1l, wih, wil, zx, nullptr, nullptr, NTOK, DINPROJ, DMODEL, nullptr, nullptr);
    // 3. dt
    dt_kernel<<<(NTOK * NHEADS) / 256, 256>>>(zx, dt_bias, dt);
    // 4. conv + silu
    conv_kernel<<<dim3((CONVDIM + 255) / 256, NTOK), 256>>>(zx, conv_w, conv_b, xbc);
    // 5. scan (128 blocks: 2 per (b,h), split along HEADDIM)
    scan_kernel<<<BATCH * NHEADS * 2, 128>>>(xbc, dt, A_log, Dp, y);
    // 6. gate + rmsnorm -> yn planes
    gate_rms_split_kernel<<<NTOK, 256>>>(y, zx, norm_w, ynh, ynl);
    // 7. out_proj + residual(x) -> x2 (fp32)
    gemm_mma<2,0><<<dim3(DMODEL / 128, NTOK / 128), 256, GEMM_SMEM>>>(
        ynh, ynl, woh, wol, x2, nullptr, nullptr, NTOK, DMODEL, DINNER, nullptr, x);
    // 8. LN2 -> h2 planes
    ln_split_kernel<<<NTOK, 256>>>(x2, ln2_w, ln2_b, h2h, h2l);
    // 9. mlp1 + bias + gelu -> mid planes
    gemm_mma<1,1><<<dim3(DMLP / 128, NTOK / 128), 256, GEMM_SMEM>>>(
        h2h, h2l, w1h, w1l, nullptr, mdh, mdl, NTOK, DMLP, DMODEL, mlp_b1, nullptr);
    // 10. mlp2 + bias + residual(x2) -> out (fp32)
    gemm_mma<3,0><<<dim3(DMODEL / 128, NTOK / 128), 256, GEMM_SMEM>>>(
        mdh, mdl, w2h, w2l, out, nullptr, nullptr, NTOK, DMODEL, DMLP, mlp_b2, x2);
}